// round 2
// baseline (speedup 1.0000x reference)
#include <cuda_runtime.h>
#include <cuda_bf16.h>
#include <cstdint>
#include <cstddef>

#define BB 32
#define CC 256
#define HWD 4096
#define RR 64

__device__ float g_pooled[BB*CC];
__device__ float g_h[BB*RR];
__device__ __nv_bfloat16 g_K0[(size_t)BB*CC*CC];
__device__ __nv_bfloat16 g_Msc[(size_t)BB*CC*CC];

// ============ K1: pooled = mean(x, HW) ============
__global__ void k_pool(const float* __restrict__ x) {
  int bc = blockIdx.x, t = threadIdx.x;
  const float4* row = (const float4*)(x + (size_t)bc * HWD);
  float s = 0.f;
  #pragma unroll
  for (int u = 0; u < 4; u++) { float4 v = row[t + u*256]; s += (v.x+v.y)+(v.z+v.w); }
  #pragma unroll
  for (int o = 16; o; o >>= 1) s += __shfl_xor_sync(0xffffffffu, s, o);
  __shared__ float ws[8];
  if ((t & 31) == 0) ws[t >> 5] = s;
  __syncthreads();
  if (t == 0) {
    float r = 0.f;
    #pragma unroll
    for (int w = 0; w < 8; w++) r += ws[w];
    g_pooled[bc] = r * (1.0f / 4096.0f);
  }
}

// ============ K2: h = silu(pooled @ w1^T + b1) ============
__global__ void k_fc1(const float* __restrict__ w1, const float* __restrict__ b1) {
  int b = blockIdx.x, r = threadIdx.x;  // 64 threads
  __shared__ float p[CC];
  for (int k = r; k < CC; k += RR) p[k] = g_pooled[b*CC + k];
  __syncthreads();
  const float4* wr = (const float4*)(w1 + (size_t)r * CC);
  float acc = b1[r];
  #pragma unroll 8
  for (int k = 0; k < 64; k++) {
    float4 w = wr[k];
    acc += w.x*p[4*k] + w.y*p[4*k+1] + w.z*p[4*k+2] + w.w*p[4*k+3];
  }
  g_h[b*RR + r] = acc / (1.0f + __expf(-acc));
}

// ============ K3: weights -> exp(w - rowmax) -> K0 (bf16) ============
__global__ void k_fc2_exp(const float* __restrict__ w2, const float* __restrict__ b2) {
  int i = blockIdx.x, j = threadIdx.x;   // 256 x 256
  __shared__ float hs[BB*RR];
  __shared__ float red[8];
  for (int tt = j; tt < BB*RR; tt += 256) hs[tt] = g_h[tt];
  float wr[64];
  const float4* w2r = (const float4*)(w2 + (size_t)(i*CC + j) * RR);
  #pragma unroll
  for (int k = 0; k < 16; k++) {
    float4 w = w2r[k];
    wr[4*k]=w.x; wr[4*k+1]=w.y; wr[4*k+2]=w.z; wr[4*k+3]=w.w;
  }
  float bv = b2[i*CC + j];
  __syncthreads();
  for (int b = 0; b < BB; b++) {
    const float* hb = hs + b*RR;
    float acc = bv;
    #pragma unroll 8
    for (int k = 0; k < 64; k++) acc += hb[k] * wr[k];
    float m = acc;
    #pragma unroll
    for (int o = 16; o; o >>= 1) m = fmaxf(m, __shfl_xor_sync(0xffffffffu, m, o));
    if ((j & 31) == 0) red[j >> 5] = m;
    __syncthreads();
    float bm = red[0];
    #pragma unroll
    for (int w = 1; w < 8; w++) bm = fmaxf(bm, red[w]);
    float e = __expf(acc - bm);
    float eo = __shfl_down_sync(0xffffffffu, e, 1);
    if ((j & 1) == 0) {
      __nv_bfloat162 pk;
      pk.x = __float2bfloat16(e); pk.y = __float2bfloat16(eo);
      *(__nv_bfloat162*)(g_K0 + ((size_t)(b*CC + i))*CC + j) = pk;
    }
    __syncthreads();
  }
}

// ============ K4: Sinkhorn (u/v scaling form), 20 iters ============
#define KP 258
#define SMEM_SINK (256*KP*2 + 512*4)
__global__ void __launch_bounds__(256, 1) k_sinkhorn(const float* __restrict__ scale) {
  extern __shared__ char smC[];
  __nv_bfloat16* Kb = (__nv_bfloat16*)smC;
  float* u = (float*)(smC + 256*KP*2);
  float* v = u + 256;
  const int b = blockIdx.x, t = threadIdx.x;
  const __nv_bfloat16* src = g_K0 + (size_t)b * (CC*CC);
  for (int idx = t; idx < 8192; idx += 256) {
    int i = idx >> 5, c8 = idx & 31;
    float4 d = *(const float4*)(src + i*CC + c8*8);
    __nv_bfloat162* dp = (__nv_bfloat162*)(Kb + i*KP + c8*8);
    const __nv_bfloat162* sp = (const __nv_bfloat162*)&d;
    dp[0]=sp[0]; dp[1]=sp[1]; dp[2]=sp[2]; dp[3]=sp[3];
  }
  v[t] = 1.0f;
  __syncthreads();
  for (int it = 0; it < 20; it++) {
    float acc = 0.f;
    const __nv_bfloat16* row = Kb + t*KP;
    #pragma unroll 8
    for (int c = 0; c < 128; c++) {
      float2 vv = *(const float2*)(v + 2*c);
      float2 kk = __bfloat1622float2(*(const __nv_bfloat162*)(row + 2*c));
      acc += kk.x*vv.x + kk.y*vv.y;
    }
    u[t] = 1.0f / (acc + 1e-12f);
    __syncthreads();
    if (t < 128) {
      float a0 = 0.f, a1 = 0.f;
      const __nv_bfloat16* cp = Kb + 2*t;
      #pragma unroll 8
      for (int i = 0; i < 256; i++) {
        float ui = u[i];
        float2 kk = __bfloat1622float2(*(const __nv_bfloat162*)(cp + i*KP));
        a0 += kk.x*ui; a1 += kk.y*ui;
      }
      v[2*t]   = 1.0f / (a0 + 1e-12f);
      v[2*t+1] = 1.0f / (a1 + 1e-12f);
    }
    __syncthreads();
  }
  float sc = scale[0];
  for (int idx = t; idx < 16384; idx += 256) {
    int i = idx >> 6, c4 = idx & 63;
    float su = sc * u[i];
    const __nv_bfloat16* rp = Kb + i*KP + 4*c4;
    float m0 = su * __bfloat162float(rp[0]) * v[4*c4+0];
    float m1 = su * __bfloat162float(rp[1]) * v[4*c4+1];
    float m2 = su * __bfloat162float(rp[2]) * v[4*c4+2];
    float m3 = su * __bfloat162float(rp[3]) * v[4*c4+3];
    __nv_bfloat162 p0, p1;
    p0.x=__float2bfloat16(m0); p0.y=__float2bfloat16(m1);
    p1.x=__float2bfloat16(m2); p1.y=__float2bfloat16(m3);
    __nv_bfloat162* dst = (__nv_bfloat162*)(g_Msc + (size_t)b*(CC*CC) + i*CC + 4*c4);
    dst[0]=p0; dst[1]=p1;
  }
}

// ============ K5: out = x + Msc @ x (bf16 HMMA) ============
#define AP 40       // A smem pitch in halves (80B rows; ldmatrix conflict-free)
#define BPITCH 136  // B smem pitch in halves (272B rows; conflict-free)
__global__ void __launch_bounds__(256, 1) k_mix(const float* __restrict__ x,
                                               float* __restrict__ out) {
  __shared__ __nv_bfloat16 As[256*AP];
  __shared__ __nv_bfloat16 Bs[16*BPITCH];
  const int b  = blockIdx.y;
  const int j0 = blockIdx.x * 128;
  const int t  = threadIdx.x;
  const int w  = t >> 5, l = t & 31;
  const int wm = (w & 3) * 64;
  const int wn = (w >> 2) * 64;

  const __nv_bfloat16* Mb = g_Msc + (size_t)b * 65536;
  const float* xb = x + (size_t)b * (CC*HWD);

  float acc[4][8][4];
  #pragma unroll
  for (int mt = 0; mt < 4; mt++)
    #pragma unroll
    for (int nt = 0; nt < 8; nt++)
      #pragma unroll
      for (int q = 0; q < 4; q++) acc[mt][nt][q] = 0.f;

  const int g = l >> 3, r = l & 7;
  const int lrow = r + (g & 1) * 8;
  const int lcol = (g >> 1) * 8;
  uint32_t a_base = (uint32_t)__cvta_generic_to_shared(As) + (uint32_t)(lrow*AP + lcol)*2;
  uint32_t b_base = (uint32_t)__cvta_generic_to_shared(Bs) + (uint32_t)(lrow*BPITCH + wn + lcol)*2;

  // staging indices
  const int ar0 = t >> 1, ah = t & 1;       // A: rows 0..127
  const int ar1 = 128 + (t >> 1);           //    rows 128..255
  const int br0 = t >> 5, bc = t & 31;      // B: k-rows 0..7
  const int br1 = 8 + (t >> 5);             //    k-rows 8..15

  uint4 sa0, sa1; float4 sb0, sb1;
  #define LOAD_TILE(kc)                                                        \
    sa0 = *(const uint4*)(Mb + (size_t)ar0*CC + (kc)*16 + ah*8);               \
    sa1 = *(const uint4*)(Mb + (size_t)ar1*CC + (kc)*16 + ah*8);               \
    sb0 = *(const float4*)(xb + (size_t)((kc)*16 + br0)*HWD + j0 + bc*4);      \
    sb1 = *(const float4*)(xb + (size_t)((kc)*16 + br1)*HWD + j0 + bc*4);
  #define STORE_TILE()                                                         \
    *(uint4*)(As + ar0*AP + ah*8) = sa0;                                       \
    *(uint4*)(As + ar1*AP + ah*8) = sa1;                                       \
    { __nv_bfloat162* bp = (__nv_bfloat162*)(Bs + br0*BPITCH + bc*4);          \
      bp[0] = __floats2bfloat162_rn(sb0.x, sb0.y);                             \
      bp[1] = __floats2bfloat162_rn(sb0.z, sb0.w);                             \
      bp = (__nv_bfloat162*)(Bs + br1*BPITCH + bc*4);                          \
      bp[0] = __floats2bfloat162_rn(sb1.x, sb1.y);                             \
      bp[1] = __floats2bfloat162_rn(sb1.z, sb1.w); }

  LOAD_TILE(0)
  STORE_TILE()
  __syncthreads();

  for (int kc = 0; kc < 16; kc++) {
    if (kc < 15) { LOAD_TILE(kc + 1) }
    // compute on current smem tile
    uint32_t bfr[8][2];
    #pragma unroll
    for (int nt2 = 0; nt2 < 4; nt2++) {
      uint32_t r0, r1, r2, r3;
      asm volatile("ldmatrix.sync.aligned.m8n8.x4.trans.shared.b16 {%0,%1,%2,%3}, [%4];"
                   : "=r"(r0), "=r"(r1), "=r"(r2), "=r"(r3)
                   : "r"(b_base + nt2*32));
      bfr[2*nt2][0]=r0; bfr[2*nt2][1]=r1; bfr[2*nt2+1][0]=r2; bfr[2*nt2+1][1]=r3;
    }
    #pragma unroll
    for (int mt = 0; mt < 4; mt++) {
      uint32_t a0, a1, a2, a3;
      asm volatile("ldmatrix.sync.aligned.m8n8.x4.shared.b16 {%0,%1,%2,%3}, [%4];"
                   : "=r"(a0), "=r"(a1), "=r"(a2), "=r"(a3)
                   : "r"(a_base + (uint32_t)(wm + mt*16)*(AP*2)));
      #pragma unroll
      for (int nt = 0; nt < 8; nt++) {
        asm volatile("mma.sync.aligned.m16n8k16.row.col.f32.bf16.bf16.f32 "
                     "{%0,%1,%2,%3}, {%4,%5,%6,%7}, {%8,%9}, {%0,%1,%2,%3};"
                     : "+f"(acc[mt][nt][0]), "+f"(acc[mt][nt][1]),
                       "+f"(acc[mt][nt][2]), "+f"(acc[mt][nt][3])
                     : "r"(a0), "r"(a1), "r"(a2), "r"(a3),
                       "r"(bfr[nt][0]), "r"(bfr[nt][1]));
      }
    }
    __syncthreads();
    if (kc < 15) { STORE_TILE() __syncthreads(); }
  }

  // epilogue: out = x + acc (scale already folded into Msc)
  const int er = l >> 2, ec = 2 * (l & 3);
  #pragma unroll
  for (int mt = 0; mt < 4; mt++) {
    #pragma unroll
    for (int nt = 0; nt < 8; nt++) {
      int row = wm + mt*16 + er;
      int col = j0 + wn + nt*8 + ec;
      size_t off = ((size_t)b*CC + row)*HWD + col;
      float2 xv = *(const float2*)(x + off);
      float2 ov; ov.x = xv.x + acc[mt][nt][0]; ov.y = xv.y + acc[mt][nt][1];
      *(float2*)(out + off) = ov;
      size_t off2 = off + (size_t)8*HWD;
      float2 xv2 = *(const float2*)(x + off2);
      float2 ov2; ov2.x = xv2.x + acc[mt][nt][2]; ov2.y = xv2.y + acc[mt][nt][3];
      *(float2*)(out + off2) = ov2;
    }
  }
}

extern "C" void kernel_launch(void* const* d_in, const int* in_sizes, int n_in,
                              void* d_out, int out_size) {
  const float* x     = (const float*)d_in[0];
  const float* w1    = (const float*)d_in[1];
  const float* b1    = (const float*)d_in[2];
  const float* w2    = (const float*)d_in[3];
  const float* b2    = (const float*)d_in[4];
  const float* scale = (const float*)d_in[5];
  float* out = (float*)d_out;

  cudaFuncSetAttribute(k_sinkhorn, cudaFuncAttributeMaxDynamicSharedMemorySize, SMEM_SINK);

  k_pool<<<BB*CC, 256>>>(x);
  k_fc1<<<BB, RR>>>(w1, b1);
  k_fc2_exp<<<CC, CC>>>(w2, b2);
  k_sinkhorn<<<BB, 256, SMEM_SINK>>>(scale);
  dim3 gmix(HWD/128, BB);
  k_mix<<<gmix, 256>>>(x, out);
}

// round 4
// speedup vs baseline: 1.0504x; 1.0504x over previous
#include <cuda_runtime.h>
#include <cuda_bf16.h>
#include <cstdint>
#include <cstddef>

#define BB 32
#define CC 256
#define HWD 4096
#define RR 64

__device__ float g_pooled[BB*CC];
__device__ float g_h[BB*RR];
__device__ __nv_bfloat16 g_K0[(size_t)BB*CC*CC];
__device__ __nv_bfloat16 g_Msc[(size_t)BB*CC*CC];
__device__ __nv_bfloat16 g_xT[(size_t)BB*HWD*CC];

__device__ __forceinline__ uint32_t s2u(const void* p) {
  return (uint32_t)__cvta_generic_to_shared(p);
}
__device__ __forceinline__ void cp16(uint32_t d, const void* s) {
  asm volatile("cp.async.cg.shared.global [%0], [%1], 16;" :: "r"(d), "l"(s));
}

// ============ K0: zero pooled accumulators ============
__global__ void k_zero() {
  int t = threadIdx.x;
  #pragma unroll
  for (int i = 0; i < 32; i++) g_pooled[t + 256*i] = 0.f;
}

// ============ K1: transpose x -> bf16 xT, partial pooled sums ============
__global__ void __launch_bounds__(256) k_poolT(const float* __restrict__ x) {
  __shared__ float ts[64*68];
  const int b = blockIdx.y, n0 = blockIdx.x * 64, t = threadIdx.x;
  const int rl = t >> 2, c4 = t & 3;
  const int nw = t & 63, cw = (t >> 6) * 16;
  for (int cg = 0; cg < 4; cg++) {
    int ch = cg*64 + rl;
    const float4* src = (const float4*)(x + ((size_t)b*CC + ch)*HWD + n0 + c4*16);
    float4 a = src[0], bq = src[1], cq = src[2], dq = src[3];
    float4* tr = (float4*)(ts + rl*68 + c4*16);
    tr[0]=a; tr[1]=bq; tr[2]=cq; tr[3]=dq;
    float s = (a.x+a.y+a.z+a.w) + (bq.x+bq.y+bq.z+bq.w)
            + (cq.x+cq.y+cq.z+cq.w) + (dq.x+dq.y+dq.z+dq.w);
    s += __shfl_xor_sync(0xffffffffu, s, 1);
    s += __shfl_xor_sync(0xffffffffu, s, 2);
    if (c4 == 0) atomicAdd(&g_pooled[b*CC + ch], s);
    __syncthreads();
    // write xT[n][c] bf16: lane-consecutive n -> conflict-free smem reads
    uint32_t pk[8];
    #pragma unroll
    for (int i = 0; i < 8; i++) {
      float v0 = ts[(cw + 2*i)*68 + nw];
      float v1 = ts[(cw + 2*i + 1)*68 + nw];
      __nv_bfloat162 p = __floats2bfloat162_rn(v0, v1);
      pk[i] = *(uint32_t*)&p;
    }
    __nv_bfloat16* dst = g_xT + ((size_t)b*HWD + n0 + nw)*CC + cg*64 + cw;
    *(uint4*)dst       = make_uint4(pk[0], pk[1], pk[2], pk[3]);
    *(uint4*)(dst + 8) = make_uint4(pk[4], pk[5], pk[6], pk[7]);
    __syncthreads();
  }
}

// ============ K2: h = silu(mean @ w1^T + b1) ============
__global__ void k_fc1(const float* __restrict__ w1, const float* __restrict__ b1) {
  int b = blockIdx.x, r = threadIdx.x;  // 64 threads
  __shared__ float p[CC];
  for (int k = r; k < CC; k += RR) p[k] = g_pooled[b*CC + k] * (1.0f/4096.0f);
  __syncthreads();
  const float4* wr = (const float4*)(w1 + (size_t)r * CC);
  float acc = b1[r];
  #pragma unroll 8
  for (int k = 0; k < 64; k++) {
    float4 w = wr[k];
    acc += w.x*p[4*k] + w.y*p[4*k+1] + w.z*p[4*k+2] + w.w*p[4*k+3];
  }
  g_h[b*RR + r] = acc / (1.0f + __expf(-acc));
}

// ============ K3: weights -> exp(w - rowmax) -> K0 (bf16) ============
__global__ void k_fc2_exp(const float* __restrict__ w2, const float* __restrict__ b2) {
  int i = blockIdx.x, j = threadIdx.x;
  __shared__ float hs[BB*RR];
  __shared__ float red[8];
  for (int tt = j; tt < BB*RR; tt += 256) hs[tt] = g_h[tt];
  float wr[64];
  const float4* w2r = (const float4*)(w2 + (size_t)(i*CC + j) * RR);
  #pragma unroll
  for (int k = 0; k < 16; k++) {
    float4 w = w2r[k];
    wr[4*k]=w.x; wr[4*k+1]=w.y; wr[4*k+2]=w.z; wr[4*k+3]=w.w;
  }
  float bv = b2[i*CC + j];
  __syncthreads();
  for (int b = 0; b < BB; b++) {
    const float* hb = hs + b*RR;
    float acc = bv;
    #pragma unroll 8
    for (int k = 0; k < 64; k++) acc += hb[k] * wr[k];
    float m = acc;
    #pragma unroll
    for (int o = 16; o; o >>= 1) m = fmaxf(m, __shfl_xor_sync(0xffffffffu, m, o));
    if ((j & 31) == 0) red[j >> 5] = m;
    __syncthreads();
    float bm = red[0];
    #pragma unroll
    for (int w = 1; w < 8; w++) bm = fmaxf(bm, red[w]);
    float e = __expf(acc - bm);
    float eo = __shfl_down_sync(0xffffffffu, e, 1);
    if ((j & 1) == 0) {
      __nv_bfloat162 pk;
      pk.x = __float2bfloat16(e); pk.y = __float2bfloat16(eo);
      *(__nv_bfloat162*)(g_K0 + ((size_t)(b*CC + i))*CC + j) = pk;
    }
    __syncthreads();
  }
}

// ============ K4: Sinkhorn u/v scaling form, 1024 threads ============
#define KP 258
#define SMEM_SINK (256*KP*2 + 8*256*4 + 512*4)
__global__ void __launch_bounds__(1024, 1) k_sinkhorn(const float* __restrict__ scale) {
  extern __shared__ char smC[];
  __nv_bfloat16* Kb = (__nv_bfloat16*)smC;
  float* red = (float*)(smC + 256*KP*2);
  float* u = red + 8*256;
  float* v = u + 256;
  const int b = blockIdx.x, t = threadIdx.x;
  const __nv_bfloat16* src = g_K0 + (size_t)b * (CC*CC);
  #pragma unroll
  for (int i = 0; i < 8; i++) {
    int idx = t + 1024*i;
    int r = idx >> 5, c8 = idx & 31;
    float4 d = *(const float4*)(src + r*CC + c8*8);
    __nv_bfloat162* dp = (__nv_bfloat162*)(Kb + r*KP + c8*8);
    const __nv_bfloat162* sp = (const __nv_bfloat162*)&d;
    dp[0]=sp[0]; dp[1]=sp[1]; dp[2]=sp[2]; dp[3]=sp[3];
  }
  if (t < 256) v[t] = 1.0f;
  __syncthreads();

  const int rr = t & 255, q = t >> 8;       // row phase: 4 col-groups of 64
  const int cp_ = t & 127, rg = t >> 7;     // col phase: 8 row-groups of 32
  for (int it = 0; it < 20; it++) {
    {
      const __nv_bfloat16* rp = Kb + rr*KP + q*64;
      const float* vp = v + q*64;
      float acc = 0.f;
      #pragma unroll
      for (int c = 0; c < 32; c++) {
        float2 kk = __bfloat1622float2(*(const __nv_bfloat162*)(rp + 2*c));
        float2 vv = *(const float2*)(vp + 2*c);
        acc += kk.x*vv.x + kk.y*vv.y;
      }
      red[q*256 + rr] = acc;
    }
    __syncthreads();
    if (t < 256) {
      float s = red[t] + red[256+t] + red[512+t] + red[768+t];
      u[t] = 1.0f / (s + 1e-12f);
    }
    __syncthreads();
    {
      const __nv_bfloat16* cp2 = Kb + (rg*32)*KP + 2*cp_;
      const float* up = u + rg*32;
      float a0 = 0.f, a1 = 0.f;
      #pragma unroll
      for (int i = 0; i < 32; i++) {
        float ui = up[i];
        float2 kk = __bfloat1622float2(*(const __nv_bfloat162*)(cp2 + i*KP));
        a0 += kk.x*ui; a1 += kk.y*ui;
      }
      float2 w2v; w2v.x = a0; w2v.y = a1;
      *(float2*)(red + rg*256 + 2*cp_) = w2v;
    }
    __syncthreads();
    if (t < 256) {
      float s = 0.f;
      #pragma unroll
      for (int g = 0; g < 8; g++) s += red[g*256 + t];
      v[t] = 1.0f / (s + 1e-12f);
    }
    __syncthreads();
  }
  float sc = scale[0];
  for (int idx = t; idx < 16384; idx += 1024) {
    int i = idx >> 6, c4 = idx & 63;
    float su = sc * u[i];
    const __nv_bfloat16* rp = Kb + i*KP + 4*c4;
    float m0 = su * __bfloat162float(rp[0]) * v[4*c4+0];
    float m1 = su * __bfloat162float(rp[1]) * v[4*c4+1];
    float m2 = su * __bfloat162float(rp[2]) * v[4*c4+2];
    float m3 = su * __bfloat162float(rp[3]) * v[4*c4+3];
    __nv_bfloat162 p0, p1;
    p0.x=__float2bfloat16(m0); p0.y=__float2bfloat16(m1);
    p1.x=__float2bfloat16(m2); p1.y=__float2bfloat16(m3);
    __nv_bfloat162* dst = (__nv_bfloat162*)(g_Msc + (size_t)b*(CC*CC) + i*CC + 4*c4);
    dst[0]=p0; dst[1]=p1;
  }
}

// ============ K5: out = x + Msc @ xT^T (bf16 HMMA, cp.async 3-stage) ============
// CTA tile: M=128, N=256, K=256, KC=32. A,B both K-major bf16, pitch 80B.
#define APITCH 80
#define ASTAGE (128*APITCH)
#define BSTAGE (256*APITCH)
#define SMEM_MIX (3*ASTAGE + 3*BSTAGE)
__global__ void __launch_bounds__(256, 1) k_mix(const float* __restrict__ x,
                                                float* __restrict__ out) {
  extern __shared__ __align__(128) char sm[];
  const int t = threadIdx.x;
  const int m0 = blockIdx.x * 128;
  const int n0 = blockIdx.y * 256;
  const int b  = blockIdx.z;
  const uint32_t s0 = s2u(sm);
  const int w = t >> 5, l = t & 31;
  const int wm = (w & 1) * 64, wn = (w >> 1) * 64;
  const int g = l >> 3, r = l & 7;
  const int lrow = r + (g & 1) * 8;
  const int lchunk = (g >> 1) * 16;

  const __nv_bfloat16* Ab = g_Msc + ((size_t)b << 16) + (size_t)m0 * CC;
  const __nv_bfloat16* Bb = g_xT  + ((size_t)b << 20) + (size_t)n0 * CC;

  // cp.async mapping
  const int arow = t >> 1, ac = t & 1;          // A: 128 rows x 2 chunk-pairs? -> 2 cp/thread
  const int brow = t >> 0;                      // B: 4 cp/thread

  #define PREFETCH(kc) {                                                        \
    uint32_t As_ = s0 + ((kc) % 3) * ASTAGE;                                    \
    uint32_t Bs_ = s0 + 3*ASTAGE + ((kc) % 3) * BSTAGE;                         \
    _Pragma("unroll")                                                           \
    for (int i_ = 0; i_ < 2; i_++) {                                            \
      int idx = t + 256*i_; int rw = idx >> 2, c_ = idx & 3;                    \
      cp16(As_ + rw*APITCH + c_*16, Ab + (size_t)rw*CC + (kc)*32 + c_*8);       \
    }                                                                           \
    _Pragma("unroll")                                                           \
    for (int i_ = 0; i_ < 4; i_++) {                                            \
      int idx = t + 256*i_; int rw = idx >> 2, c_ = idx & 3;                    \
      cp16(Bs_ + rw*APITCH + c_*16, Bb + (size_t)rw*CC + (kc)*32 + c_*8);       \
    }                                                                           \
    asm volatile("cp.async.commit_group;");                                     \
  }

  float acc[4][8][4];
  #pragma unroll
  for (int mt = 0; mt < 4; mt++)
    #pragma unroll
    for (int nt = 0; nt < 8; nt++)
      #pragma unroll
      for (int qq = 0; qq < 4; qq++) acc[mt][nt][qq] = 0.f;

  PREFETCH(0)
  PREFETCH(1)

  for (int kc = 0; kc < 8; kc++) {
    if (kc < 6) asm volatile("cp.async.wait_group 1;" ::: "memory");
    else        asm volatile("cp.async.wait_group 0;" ::: "memory");
    __syncthreads();
    uint32_t Ast = s0 + (kc % 3) * ASTAGE;
    uint32_t Bst = s0 + 3*ASTAGE + (kc % 3) * BSTAGE;
    uint32_t abase = Ast + (uint32_t)(wm + lrow)*APITCH + lchunk;
    uint32_t bbase = Bst + (uint32_t)(wn + lrow)*APITCH + lchunk;
    #pragma unroll
    for (int ks = 0; ks < 2; ks++) {
      uint32_t bfr[8][2];
      #pragma unroll
      for (int ng = 0; ng < 4; ng++) {
        uint32_t r0, r1, r2, r3;
        asm volatile("ldmatrix.sync.aligned.m8n8.x4.shared.b16 {%0,%1,%2,%3}, [%4];"
                     : "=r"(r0), "=r"(r1), "=r"(r2), "=r"(r3)
                     : "r"(bbase + ng*16*APITCH + ks*32));
        bfr[2*ng][0]=r0; bfr[2*ng+1][0]=r1; bfr[2*ng][1]=r2; bfr[2*ng+1][1]=r3;
      }
      #pragma unroll
      for (int mt = 0; mt < 4; mt++) {
        uint32_t a0, a1, a2, a3;
        asm volatile("ldmatrix.sync.aligned.m8n8.x4.shared.b16 {%0,%1,%2,%3}, [%4];"
                     : "=r"(a0), "=r"(a1), "=r"(a2), "=r"(a3)
                     : "r"(abase + mt*16*APITCH + ks*32));
        #pragma unroll
        for (int nt = 0; nt < 8; nt++) {
          asm volatile("mma.sync.aligned.m16n8k16.row.col.f32.bf16.bf16.f32 "
                       "{%0,%1,%2,%3}, {%4,%5,%6,%7}, {%8,%9}, {%0,%1,%2,%3};"
                       : "+f"(acc[mt][nt][0]), "+f"(acc[mt][nt][1]),
                         "+f"(acc[mt][nt][2]), "+f"(acc[mt][nt][3])
                       : "r"(a0), "r"(a1), "r"(a2), "r"(a3),
                         "r"(bfr[nt][0]), "r"(bfr[nt][1]));
        }
      }
    }
    __syncthreads();
    if (kc + 2 < 8) PREFETCH(kc + 2)
  }

  // epilogue: out = x + acc (scale folded into Msc)
  const float* xb = x   + ((size_t)b*CC + m0)*HWD + n0;
  float*       ob = out + ((size_t)b*CC + m0)*HWD + n0;
  const int er = l >> 2, ec = 2 * (l & 3);
  #pragma unroll
  for (int mt = 0; mt < 4; mt++) {
    #pragma unroll
    for (int nt = 0; nt < 8; nt++) {
      int row = wm + mt*16 + er;
      int col = wn + nt*8 + ec;
      size_t off = (size_t)row*HWD + col;
      float2 xv = *(const float2*)(xb + off);
      float2 ov; ov.x = xv.x + acc[mt][nt][0]; ov.y = xv.y + acc[mt][nt][1];
      *(float2*)(ob + off) = ov;
      size_t off2 = off + (size_t)8*HWD;
      float2 xv2 = *(const float2*)(xb + off2);
      float2 ov2; ov2.x = xv2.x + acc[mt][nt][2]; ov2.y = xv2.y + acc[mt][nt][3];
      *(float2*)(ob + off2) = ov2;
    }
  }
}

extern "C" void kernel_launch(void* const* d_in, const int* in_sizes, int n_in,
                              void* d_out, int out_size) {
  const float* x     = (const float*)d_in[0];
  const float* w1    = (const float*)d_in[1];
  const float* b1    = (const float*)d_in[2];
  const float* w2    = (const float*)d_in[3];
  const float* b2    = (const float*)d_in[4];
  const float* scale = (const float*)d_in[5];
  float* out = (float*)d_out;

  cudaFuncSetAttribute(k_sinkhorn, cudaFuncAttributeMaxDynamicSharedMemorySize, SMEM_SINK);
  cudaFuncSetAttribute(k_mix, cudaFuncAttributeMaxDynamicSharedMemorySize, SMEM_MIX);

  k_zero<<<1, 256>>>();
  dim3 gpool(HWD/64, BB);
  k_poolT<<<gpool, 256>>>(x);
  k_fc1<<<BB, RR>>>(w1, b1);
  k_fc2_exp<<<CC, CC>>>(w2, b2);
  k_sinkhorn<<<BB, 1024, SMEM_SINK>>>(scale);
  dim3 gmix(CC/128, HWD/256, BB);
  k_mix<<<gmix, 256, SMEM_MIX>>>(x, out);
}

// round 5
// speedup vs baseline: 1.2261x; 1.1673x over previous
#include <cuda_runtime.h>
#include <cuda_bf16.h>
#include <cstdint>
#include <cstddef>

#define BB 32
#define CC 256
#define HWD 4096
#define RR 64

__device__ float g_pooled[BB*CC];
__device__ float g_h[BB*RR];
__device__ __nv_bfloat16 g_K0[(size_t)BB*CC*CC];
__device__ __nv_bfloat16 g_Msc[(size_t)BB*CC*CC];
__device__ __nv_bfloat16 g_xT[(size_t)BB*HWD*CC];

__device__ __forceinline__ uint32_t s2u(const void* p) {
  return (uint32_t)__cvta_generic_to_shared(p);
}
__device__ __forceinline__ void cp16(uint32_t d, const void* s) {
  asm volatile("cp.async.cg.shared.global [%0], [%1], 16;" :: "r"(d), "l"(s));
}

// ============ K0: zero pooled accumulators ============
__global__ void k_zero() {
  int t = threadIdx.x;
  #pragma unroll
  for (int i = 0; i < 32; i++) g_pooled[t + 256*i] = 0.f;
}

// ============ K1: transpose x -> bf16 xT, partial pooled sums ============
__global__ void __launch_bounds__(256) k_poolT(const float* __restrict__ x) {
  __shared__ float ts[64*68];
  const int b = blockIdx.y, n0 = blockIdx.x * 64, t = threadIdx.x;
  const int rl = t >> 2, c4 = t & 3;
  const int nw = t & 63, cw = (t >> 6) * 16;
  for (int cg = 0; cg < 4; cg++) {
    int ch = cg*64 + rl;
    const float4* src = (const float4*)(x + ((size_t)b*CC + ch)*HWD + n0 + c4*16);
    float4 a = src[0], bq = src[1], cq = src[2], dq = src[3];
    float4* tr = (float4*)(ts + rl*68 + c4*16);
    tr[0]=a; tr[1]=bq; tr[2]=cq; tr[3]=dq;
    float s = (a.x+a.y+a.z+a.w) + (bq.x+bq.y+bq.z+bq.w)
            + (cq.x+cq.y+cq.z+cq.w) + (dq.x+dq.y+dq.z+dq.w);
    s += __shfl_xor_sync(0xffffffffu, s, 1);
    s += __shfl_xor_sync(0xffffffffu, s, 2);
    if (c4 == 0) atomicAdd(&g_pooled[b*CC + ch], s);
    __syncthreads();
    uint32_t pk[8];
    #pragma unroll
    for (int i = 0; i < 8; i++) {
      float v0 = ts[(cw + 2*i)*68 + nw];
      float v1 = ts[(cw + 2*i + 1)*68 + nw];
      __nv_bfloat162 p = __floats2bfloat162_rn(v0, v1);
      pk[i] = *(uint32_t*)&p;
    }
    __nv_bfloat16* dst = g_xT + ((size_t)b*HWD + n0 + nw)*CC + cg*64 + cw;
    *(uint4*)dst       = make_uint4(pk[0], pk[1], pk[2], pk[3]);
    *(uint4*)(dst + 8) = make_uint4(pk[4], pk[5], pk[6], pk[7]);
    __syncthreads();
  }
}

// ============ K2: h = silu(mean @ w1^T + b1) ============
__global__ void k_fc1(const float* __restrict__ w1, const float* __restrict__ b1) {
  int b = blockIdx.x, r = threadIdx.x;  // 64 threads
  __shared__ float p[CC];
  for (int k = r; k < CC; k += RR) p[k] = g_pooled[b*CC + k] * (1.0f/4096.0f);
  __syncthreads();
  const float4* wr = (const float4*)(w1 + (size_t)r * CC);
  float acc = b1[r];
  #pragma unroll 8
  for (int k = 0; k < 64; k++) {
    float4 w = wr[k];
    acc += w.x*p[4*k] + w.y*p[4*k+1] + w.z*p[4*k+2] + w.w*p[4*k+3];
  }
  g_h[b*RR + r] = acc / (1.0f + __expf(-acc));
}

// ============ K3: weights -> exp(w - rowmax) -> K0 (bf16) ============
// acc[32] in regs (one per batch), w2 row streamed as float4 (no spill),
// h reads are warp-uniform broadcasts, 2 total syncs.
__global__ void __launch_bounds__(256) k_fc2_exp(const float* __restrict__ w2,
                                                 const float* __restrict__ b2) {
  const int i = blockIdx.x, j = threadIdx.x;
  const int w = j >> 5, l = j & 31;
  __shared__ float hs[BB*RR];
  __shared__ float red[8*32];
  for (int tt = j; tt < BB*RR; tt += 256) hs[tt] = g_h[tt];
  __syncthreads();

  const float4* w2r = (const float4*)(w2 + (size_t)(i*CC + j) * RR);
  const float bv = b2[i*CC + j];
  float acc[32];
  #pragma unroll
  for (int b = 0; b < 32; b++) acc[b] = bv;
  #pragma unroll
  for (int k4 = 0; k4 < 16; k4++) {
    float4 wv = w2r[k4];
    #pragma unroll
    for (int b = 0; b < 32; b++) {
      const float* hb = hs + b*64 + k4*4;
      acc[b] += wv.x*hb[0] + wv.y*hb[1] + wv.z*hb[2] + wv.w*hb[3];
    }
  }
  // per-batch row max: warp reduce, lane b stages warp w's max
  #pragma unroll
  for (int b = 0; b < 32; b++) {
    float m = acc[b];
    #pragma unroll
    for (int o = 16; o; o >>= 1) m = fmaxf(m, __shfl_xor_sync(0xffffffffu, m, o));
    if (l == b) red[w*32 + b] = m;
  }
  __syncthreads();
  #pragma unroll
  for (int b = 0; b < 32; b++) {
    float bm = red[b];
    #pragma unroll
    for (int ww = 1; ww < 8; ww++) bm = fmaxf(bm, red[ww*32 + b]);
    float e = __expf(acc[b] - bm);
    float eo = __shfl_down_sync(0xffffffffu, e, 1);
    if ((j & 1) == 0) {
      __nv_bfloat162 pk;
      pk.x = __float2bfloat16(e); pk.y = __float2bfloat16(eo);
      *(__nv_bfloat162*)(g_K0 + ((size_t)(b*CC + i))*CC + j) = pk;
    }
  }
}

// ============ K4: Sinkhorn u/v scaling form, 1024 threads ============
#define KP 258
#define SMEM_SINK (256*KP*2 + 8*256*4 + 512*4)
__global__ void __launch_bounds__(1024, 1) k_sinkhorn(const float* __restrict__ scale) {
  extern __shared__ char smC[];
  __nv_bfloat16* Kb = (__nv_bfloat16*)smC;
  float* red = (float*)(smC + 256*KP*2);
  float* u = red + 8*256;
  float* v = u + 256;
  const int b = blockIdx.x, t = threadIdx.x;
  const __nv_bfloat16* src = g_K0 + (size_t)b * (CC*CC);
  #pragma unroll
  for (int i = 0; i < 8; i++) {
    int idx = t + 1024*i;
    int r = idx >> 5, c8 = idx & 31;
    float4 d = *(const float4*)(src + r*CC + c8*8);
    __nv_bfloat162* dp = (__nv_bfloat162*)(Kb + r*KP + c8*8);
    const __nv_bfloat162* sp = (const __nv_bfloat162*)&d;
    dp[0]=sp[0]; dp[1]=sp[1]; dp[2]=sp[2]; dp[3]=sp[3];
  }
  if (t < 256) v[t] = 1.0f;
  __syncthreads();

  const int rr = t & 255, q = t >> 8;
  const int cp_ = t & 127, rg = t >> 7;
  for (int it = 0; it < 20; it++) {
    {
      const __nv_bfloat16* rp = Kb + rr*KP + q*64;
      const float* vp = v + q*64;
      float acc = 0.f;
      #pragma unroll
      for (int c = 0; c < 32; c++) {
        float2 kk = __bfloat1622float2(*(const __nv_bfloat162*)(rp + 2*c));
        float2 vv = *(const float2*)(vp + 2*c);
        acc += kk.x*vv.x + kk.y*vv.y;
      }
      red[q*256 + rr] = acc;
    }
    __syncthreads();
    if (t < 256) {
      float s = red[t] + red[256+t] + red[512+t] + red[768+t];
      u[t] = 1.0f / (s + 1e-12f);
    }
    __syncthreads();
    {
      const __nv_bfloat16* cp2 = Kb + (rg*32)*KP + 2*cp_;
      const float* up = u + rg*32;
      float a0 = 0.f, a1 = 0.f;
      #pragma unroll
      for (int i = 0; i < 32; i++) {
        float ui = up[i];
        float2 kk = __bfloat1622float2(*(const __nv_bfloat162*)(cp2 + i*KP));
        a0 += kk.x*ui; a1 += kk.y*ui;
      }
      float2 w2v; w2v.x = a0; w2v.y = a1;
      *(float2*)(red + rg*256 + 2*cp_) = w2v;
    }
    __syncthreads();
    if (t < 256) {
      float s = 0.f;
      #pragma unroll
      for (int g = 0; g < 8; g++) s += red[g*256 + t];
      v[t] = 1.0f / (s + 1e-12f);
    }
    __syncthreads();
  }
  float sc = scale[0];
  for (int idx = t; idx < 16384; idx += 1024) {
    int i = idx >> 6, c4 = idx & 63;
    float su = sc * u[i];
    const __nv_bfloat16* rp = Kb + i*KP + 4*c4;
    float m0 = su * __bfloat162float(rp[0]) * v[4*c4+0];
    float m1 = su * __bfloat162float(rp[1]) * v[4*c4+1];
    float m2 = su * __bfloat162float(rp[2]) * v[4*c4+2];
    float m3 = su * __bfloat162float(rp[3]) * v[4*c4+3];
    __nv_bfloat162 p0, p1;
    p0.x=__float2bfloat16(m0); p0.y=__float2bfloat16(m1);
    p1.x=__float2bfloat16(m2); p1.y=__float2bfloat16(m3);
    __nv_bfloat162* dst = (__nv_bfloat162*)(g_Msc + (size_t)b*(CC*CC) + i*CC + 4*c4);
    dst[0]=p0; dst[1]=p1;
  }
}

// ============ K5: out = x + Msc @ xT^T (bf16 HMMA, cp.async 3-stage) ============
#define APITCH 80
#define ASTAGE (128*APITCH)
#define BSTAGE (256*APITCH)
#define SMEM_MIX (3*ASTAGE + 3*BSTAGE)
__global__ void __launch_bounds__(256, 1) k_mix(const float* __restrict__ x,
                                                float* __restrict__ out) {
  extern __shared__ __align__(128) char sm[];
  const int t = threadIdx.x;
  const int m0 = blockIdx.x * 128;
  const int n0 = blockIdx.y * 256;
  const int b  = blockIdx.z;
  const uint32_t s0 = s2u(sm);
  const int w = t >> 5, l = t & 31;
  const int wm = (w & 1) * 64, wn = (w >> 1) * 64;
  const int g = l >> 3, r = l & 7;
  const int lrow = r + (g & 1) * 8;
  const int lchunk = (g >> 1) * 16;

  const __nv_bfloat16* Ab = g_Msc + ((size_t)b << 16) + (size_t)m0 * CC;
  const __nv_bfloat16* Bb = g_xT  + ((size_t)b << 20) + (size_t)n0 * CC;

  #define PREFETCH(kc) {                                                        \
    uint32_t As_ = s0 + ((kc) % 3) * ASTAGE;                                    \
    uint32_t Bs_ = s0 + 3*ASTAGE + ((kc) % 3) * BSTAGE;                         \
    _Pragma("unroll")                                                           \
    for (int i_ = 0; i_ < 2; i_++) {                                            \
      int idx = t + 256*i_; int rw = idx >> 2, c_ = idx & 3;                    \
      cp16(As_ + rw*APITCH + c_*16, Ab + (size_t)rw*CC + (kc)*32 + c_*8);       \
    }                                                                           \
    _Pragma("unroll")                                                           \
    for (int i_ = 0; i_ < 4; i_++) {                                            \
      int idx = t + 256*i_; int rw = idx >> 2, c_ = idx & 3;                    \
      cp16(Bs_ + rw*APITCH + c_*16, Bb + (size_t)rw*CC + (kc)*32 + c_*8);       \
    }                                                                           \
    asm volatile("cp.async.commit_group;");                                     \
  }

  float acc[4][8][4];
  #pragma unroll
  for (int mt = 0; mt < 4; mt++)
    #pragma unroll
    for (int nt = 0; nt < 8; nt++)
      #pragma unroll
      for (int qq = 0; qq < 4; qq++) acc[mt][nt][qq] = 0.f;

  PREFETCH(0)
  PREFETCH(1)

  for (int kc = 0; kc < 8; kc++) {
    if (kc < 6) asm volatile("cp.async.wait_group 1;" ::: "memory");
    else        asm volatile("cp.async.wait_group 0;" ::: "memory");
    __syncthreads();
    uint32_t Ast = s0 + (kc % 3) * ASTAGE;
    uint32_t Bst = s0 + 3*ASTAGE + (kc % 3) * BSTAGE;
    uint32_t abase = Ast + (uint32_t)(wm + lrow)*APITCH + lchunk;
    uint32_t bbase = Bst + (uint32_t)(wn + lrow)*APITCH + lchunk;
    #pragma unroll
    for (int ks = 0; ks < 2; ks++) {
      uint32_t bfr[8][2];
      #pragma unroll
      for (int ng = 0; ng < 4; ng++) {
        uint32_t r0, r1, r2, r3;
        asm volatile("ldmatrix.sync.aligned.m8n8.x4.shared.b16 {%0,%1,%2,%3}, [%4];"
                     : "=r"(r0), "=r"(r1), "=r"(r2), "=r"(r3)
                     : "r"(bbase + ng*16*APITCH + ks*32));
        bfr[2*ng][0]=r0; bfr[2*ng+1][0]=r1; bfr[2*ng][1]=r2; bfr[2*ng+1][1]=r3;
      }
      #pragma unroll
      for (int mt = 0; mt < 4; mt++) {
        uint32_t a0, a1, a2, a3;
        asm volatile("ldmatrix.sync.aligned.m8n8.x4.shared.b16 {%0,%1,%2,%3}, [%4];"
                     : "=r"(a0), "=r"(a1), "=r"(a2), "=r"(a3)
                     : "r"(abase + mt*16*APITCH + ks*32));
        #pragma unroll
        for (int nt = 0; nt < 8; nt++) {
          asm volatile("mma.sync.aligned.m16n8k16.row.col.f32.bf16.bf16.f32 "
                       "{%0,%1,%2,%3}, {%4,%5,%6,%7}, {%8,%9}, {%0,%1,%2,%3};"
                       : "+f"(acc[mt][nt][0]), "+f"(acc[mt][nt][1]),
                         "+f"(acc[mt][nt][2]), "+f"(acc[mt][nt][3])
                       : "r"(a0), "r"(a1), "r"(a2), "r"(a3),
                         "r"(bfr[nt][0]), "r"(bfr[nt][1]));
        }
      }
    }
    __syncthreads();
    if (kc + 2 < 8) PREFETCH(kc + 2)
  }

  const float* xb = x   + ((size_t)b*CC + m0)*HWD + n0;
  float*       ob = out + ((size_t)b*CC + m0)*HWD + n0;
  const int er = l >> 2, ec = 2 * (l & 3);
  #pragma unroll
  for (int mt = 0; mt < 4; mt++) {
    #pragma unroll
    for (int nt = 0; nt < 8; nt++) {
      int row = wm + mt*16 + er;
      int col = wn + nt*8 + ec;
      size_t off = (size_t)row*HWD + col;
      float2 xv = *(const float2*)(xb + off);
      float2 ov; ov.x = xv.x + acc[mt][nt][0]; ov.y = xv.y + acc[mt][nt][1];
      *(float2*)(ob + off) = ov;
      size_t off2 = off + (size_t)8*HWD;
      float2 xv2 = *(const float2*)(xb + off2);
      float2 ov2; ov2.x = xv2.x + acc[mt][nt][2]; ov2.y = xv2.y + acc[mt][nt][3];
      *(float2*)(ob + off2) = ov2;
    }
  }
}

extern "C" void kernel_launch(void* const* d_in, const int* in_sizes, int n_in,
                              void* d_out, int out_size) {
  const float* x     = (const float*)d_in[0];
  const float* w1    = (const float*)d_in[1];
  const float* b1    = (const float*)d_in[2];
  const float* w2    = (const float*)d_in[3];
  const float* b2    = (const float*)d_in[4];
  const float* scale = (const float*)d_in[5];
  float* out = (float*)d_out;

  cudaFuncSetAttribute(k_sinkhorn, cudaFuncAttributeMaxDynamicSharedMemorySize, SMEM_SINK);
  cudaFuncSetAttribute(k_mix, cudaFuncAttributeMaxDynamicSharedMemorySize, SMEM_MIX);

  k_zero<<<1, 256>>>();
  dim3 gpool(HWD/64, BB);
  k_poolT<<<gpool, 256>>>(x);
  k_fc1<<<BB, RR>>>(w1, b1);
  k_fc2_exp<<<CC, CC>>>(w2, b2);
  k_sinkhorn<<<BB, 1024, SMEM_SINK>>>(scale);
  dim3 gmix(CC/128, HWD/256, BB);
  k_mix<<<gmix, 256, SMEM_MIX>>>(x, out);
}

// round 6
// speedup vs baseline: 1.3026x; 1.0624x over previous
#include <cuda_runtime.h>
#include <cuda_bf16.h>
#include <cstdint>
#include <cstddef>

#define BB 32
#define CC 256
#define HWD 4096
#define RR 64

__device__ float g_pooled[BB*CC];
__device__ float g_h[BB*RR];
__device__ __nv_bfloat16 g_K0[(size_t)BB*CC*CC];
__device__ uint8_t g_M8[(size_t)BB*CC*CC];        // e4m3, M*64
__device__ uint8_t g_x8[(size_t)BB*HWD*CC];       // e4m3 x^T

__device__ __forceinline__ uint32_t s2u(const void* p) {
  return (uint32_t)__cvta_generic_to_shared(p);
}
__device__ __forceinline__ void cp16(uint32_t d, const void* s) {
  asm volatile("cp.async.cg.shared.global [%0], [%1], 16;" :: "r"(d), "l"(s));
}
// pack two floats -> e4m3x2 (lo, hi)
__device__ __forceinline__ uint32_t fp8x2(float lo, float hi) {
  uint16_t r;
  asm("cvt.rn.satfinite.e4m3x2.f32 %0, %1, %2;" : "=h"(r) : "f"(hi), "f"(lo));
  return (uint32_t)r;
}

// ============ K1: transpose x -> e4m3 x8, partial pooled sums ============
__global__ void __launch_bounds__(256) k_poolT(const float* __restrict__ x) {
  __shared__ float ts[64*68];
  const int b = blockIdx.y, n0 = blockIdx.x * 64, t = threadIdx.x;
  const int rl = t >> 2, c4 = t & 3;
  const int nw = t & 63, cw = (t >> 6) * 16;
  for (int cg = 0; cg < 4; cg++) {
    int ch = cg*64 + rl;
    const float4* src = (const float4*)(x + ((size_t)b*CC + ch)*HWD + n0 + c4*16);
    float4 a = src[0], bq = src[1], cq = src[2], dq = src[3];
    float4* tr = (float4*)(ts + rl*68 + c4*16);
    tr[0]=a; tr[1]=bq; tr[2]=cq; tr[3]=dq;
    float s = (a.x+a.y+a.z+a.w) + (bq.x+bq.y+bq.z+bq.w)
            + (cq.x+cq.y+cq.z+cq.w) + (dq.x+dq.y+dq.z+dq.w);
    s += __shfl_xor_sync(0xffffffffu, s, 1);
    s += __shfl_xor_sync(0xffffffffu, s, 2);
    if (c4 == 0) atomicAdd(&g_pooled[b*CC + ch], s);
    __syncthreads();
    uint32_t pk[4];
    #pragma unroll
    for (int i = 0; i < 4; i++) {
      float v0 = ts[(cw + 4*i + 0)*68 + nw];
      float v1 = ts[(cw + 4*i + 1)*68 + nw];
      float v2 = ts[(cw + 4*i + 2)*68 + nw];
      float v3 = ts[(cw + 4*i + 3)*68 + nw];
      pk[i] = fp8x2(v0, v1) | (fp8x2(v2, v3) << 16);
    }
    uint8_t* dst = g_x8 + ((size_t)b*HWD + n0 + nw)*CC + cg*64 + cw;
    *(uint4*)dst = make_uint4(pk[0], pk[1], pk[2], pk[3]);
    __syncthreads();
  }
}

// ============ K2: h = silu(mean @ w1^T + b1); zero pooled for next replay ===
__global__ void k_fc1(const float* __restrict__ w1, const float* __restrict__ b1) {
  int b = blockIdx.x, r = threadIdx.x;  // 64 threads
  __shared__ float p[CC];
  for (int k = r; k < CC; k += RR) p[k] = g_pooled[b*CC + k] * (1.0f/4096.0f);
  __syncthreads();
  for (int k = r; k < CC; k += RR) g_pooled[b*CC + k] = 0.f;
  const float4* wr = (const float4*)(w1 + (size_t)r * CC);
  float acc = b1[r];
  #pragma unroll 8
  for (int k = 0; k < 64; k++) {
    float4 w = wr[k];
    acc += w.x*p[4*k] + w.y*p[4*k+1] + w.z*p[4*k+2] + w.w*p[4*k+3];
  }
  g_h[b*RR + r] = acc / (1.0f + __expf(-acc));
}

// ============ K3: weights -> exp(w - rowmax) -> K0 (bf16) ============
__global__ void __launch_bounds__(256) k_fc2_exp(const float* __restrict__ w2,
                                                 const float* __restrict__ b2) {
  const int i = blockIdx.x, j = threadIdx.x;
  const int w = j >> 5, l = j & 31;
  __shared__ float hs[BB*RR];
  __shared__ float red[8*32];
  for (int tt = j; tt < BB*RR; tt += 256) hs[tt] = g_h[tt];
  __syncthreads();

  const float4* w2r = (const float4*)(w2 + (size_t)(i*CC + j) * RR);
  const float bv = b2[i*CC + j];
  float acc[32];
  #pragma unroll
  for (int b = 0; b < 32; b++) acc[b] = bv;
  #pragma unroll
  for (int k4 = 0; k4 < 16; k4++) {
    float4 wv = w2r[k4];
    #pragma unroll
    for (int b = 0; b < 32; b++) {
      const float* hb = hs + b*64 + k4*4;
      acc[b] += wv.x*hb[0] + wv.y*hb[1] + wv.z*hb[2] + wv.w*hb[3];
    }
  }
  #pragma unroll
  for (int b = 0; b < 32; b++) {
    float m = acc[b];
    #pragma unroll
    for (int o = 16; o; o >>= 1) m = fmaxf(m, __shfl_xor_sync(0xffffffffu, m, o));
    if (l == b) red[w*32 + b] = m;
  }
  __syncthreads();
  #pragma unroll
  for (int b = 0; b < 32; b++) {
    float bm = red[b];
    #pragma unroll
    for (int ww = 1; ww < 8; ww++) bm = fmaxf(bm, red[ww*32 + b]);
    float e = __expf(acc[b] - bm);
    float eo = __shfl_down_sync(0xffffffffu, e, 1);
    if ((j & 1) == 0) {
      __nv_bfloat162 pk;
      pk.x = __float2bfloat16(e); pk.y = __float2bfloat16(eo);
      *(__nv_bfloat162*)(g_K0 + ((size_t)(b*CC + i))*CC + j) = pk;
    }
  }
}

// ============ K4: Sinkhorn u/v scaling form, 1024 threads ============
#define KP 258
#define SMEM_SINK (256*KP*2 + 8*256*4 + 512*4)
__global__ void __launch_bounds__(1024, 1) k_sinkhorn() {
  extern __shared__ char smC[];
  __nv_bfloat16* Kb = (__nv_bfloat16*)smC;
  float* red = (float*)(smC + 256*KP*2);
  float* u = red + 8*256;
  float* v = u + 256;
  const int b = blockIdx.x, t = threadIdx.x;
  const __nv_bfloat16* src = g_K0 + (size_t)b * (CC*CC);
  #pragma unroll
  for (int i = 0; i < 8; i++) {
    int idx = t + 1024*i;
    int r = idx >> 5, c8 = idx & 31;
    float4 d = *(const float4*)(src + r*CC + c8*8);
    __nv_bfloat162* dp = (__nv_bfloat162*)(Kb + r*KP + c8*8);
    const __nv_bfloat162* sp = (const __nv_bfloat162*)&d;
    dp[0]=sp[0]; dp[1]=sp[1]; dp[2]=sp[2]; dp[3]=sp[3];
  }
  if (t < 256) v[t] = 1.0f;
  __syncthreads();

  const int rr = t & 255, q = t >> 8;
  const int cp_ = t & 127, rg = t >> 7;
  for (int it = 0; it < 20; it++) {
    {
      const __nv_bfloat16* rp = Kb + rr*KP + q*64;
      const float* vp = v + q*64;
      float acc = 0.f;
      #pragma unroll
      for (int c = 0; c < 32; c++) {
        float2 kk = __bfloat1622float2(*(const __nv_bfloat162*)(rp + 2*c));
        float2 vv = *(const float2*)(vp + 2*c);
        acc += kk.x*vv.x + kk.y*vv.y;
      }
      red[q*256 + rr] = acc;
    }
    __syncthreads();
    if (t < 256) {
      float s = red[t] + red[256+t] + red[512+t] + red[768+t];
      u[t] = 1.0f / (s + 1e-12f);
    }
    __syncthreads();
    {
      const __nv_bfloat16* cp2 = Kb + (rg*32)*KP + 2*cp_;
      const float* up = u + rg*32;
      float a0 = 0.f, a1 = 0.f;
      #pragma unroll
      for (int i = 0; i < 32; i++) {
        float ui = up[i];
        float2 kk = __bfloat1622float2(*(const __nv_bfloat162*)(cp2 + i*KP));
        a0 += kk.x*ui; a1 += kk.y*ui;
      }
      float2 w2v; w2v.x = a0; w2v.y = a1;
      *(float2*)(red + rg*256 + 2*cp_) = w2v;
    }
    __syncthreads();
    if (t < 256) {
      float s = 0.f;
      #pragma unroll
      for (int g = 0; g < 8; g++) s += red[g*256 + t];
      v[t] = 1.0f / (s + 1e-12f);
    }
    __syncthreads();
  }
  // write M8 = 64 * u_i * K0 * v_j as e4m3 (scale applied in mix epilogue)
  for (int idx = t; idx < 16384; idx += 1024) {
    int i = idx >> 6, c4 = idx & 63;
    float su = 64.0f * u[i];
    const __nv_bfloat16* rp = Kb + i*KP + 4*c4;
    float m0 = su * __bfloat162float(rp[0]) * v[4*c4+0];
    float m1 = su * __bfloat162float(rp[1]) * v[4*c4+1];
    float m2 = su * __bfloat162float(rp[2]) * v[4*c4+2];
    float m3 = su * __bfloat162float(rp[3]) * v[4*c4+3];
    uint32_t pk = fp8x2(m0, m1) | (fp8x2(m2, m3) << 16);
    *(uint32_t*)(g_M8 + (size_t)b*(CC*CC) + i*CC + 4*c4) = pk;
  }
}

// ============ K5: out = x + (scale/64) * M8 @ x8^T (e4m3 QMMA) ============
// CTA tile M=128, N=256, K=256; chunk KC=64 bytes; 3-stage cp.async.
#define APITCH 80
#define ASTAGE (128*APITCH)
#define BSTAGE (256*APITCH)
#define SMEM_MIX (3*ASTAGE + 3*BSTAGE)
__global__ void __launch_bounds__(256, 1) k_mix(const float* __restrict__ x,
                                                const float* __restrict__ scale,
                                                float* __restrict__ out) {
  extern __shared__ __align__(128) char sm[];
  const int t = threadIdx.x;
  const int m0 = blockIdx.x * 128;
  const int n0 = blockIdx.y * 256;
  const int b  = blockIdx.z;
  const uint32_t s0 = s2u(sm);
  const int w = t >> 5, l = t & 31;
  const int wm = (w & 1) * 64, wn = (w >> 1) * 64;
  const int g = l >> 3, r = l & 7;
  const int lrow = r + (g & 1) * 8;
  const int lchunk = (g >> 1) * 16;

  const uint8_t* Ab = g_M8 + ((size_t)b << 16) + (size_t)m0 * CC;
  const uint8_t* Bb = g_x8 + ((size_t)b << 20) + (size_t)n0 * CC;

  #define PREFETCH(kc) {                                                        \
    uint32_t As_ = s0 + ((kc) % 3) * ASTAGE;                                    \
    uint32_t Bs_ = s0 + 3*ASTAGE + ((kc) % 3) * BSTAGE;                         \
    _Pragma("unroll")                                                           \
    for (int i_ = 0; i_ < 2; i_++) {                                            \
      int idx = t + 256*i_; int rw = idx >> 2, c_ = idx & 3;                    \
      cp16(As_ + rw*APITCH + c_*16, Ab + (size_t)rw*CC + (kc)*64 + c_*16);      \
    }                                                                           \
    _Pragma("unroll")                                                           \
    for (int i_ = 0; i_ < 4; i_++) {                                            \
      int idx = t + 256*i_; int rw = idx >> 2, c_ = idx & 3;                    \
      cp16(Bs_ + rw*APITCH + c_*16, Bb + (size_t)rw*CC + (kc)*64 + c_*16);      \
    }                                                                           \
    asm volatile("cp.async.commit_group;");                                     \
  }

  float acc[4][8][4];
  #pragma unroll
  for (int mt = 0; mt < 4; mt++)
    #pragma unroll
    for (int nt = 0; nt < 8; nt++)
      #pragma unroll
      for (int qq = 0; qq < 4; qq++) acc[mt][nt][qq] = 0.f;

  PREFETCH(0)
  PREFETCH(1)

  for (int kc = 0; kc < 4; kc++) {
    if (kc < 3) asm volatile("cp.async.wait_group 1;" ::: "memory");
    else        asm volatile("cp.async.wait_group 0;" ::: "memory");
    __syncthreads();
    uint32_t Ast = s0 + (kc % 3) * ASTAGE;
    uint32_t Bst = s0 + 3*ASTAGE + (kc % 3) * BSTAGE;
    uint32_t abase = Ast + (uint32_t)(wm + lrow)*APITCH + lchunk;
    uint32_t bbase = Bst + (uint32_t)(wn + lrow)*APITCH + lchunk;
    #pragma unroll
    for (int ks = 0; ks < 2; ks++) {
      uint32_t bfr[8][2];
      #pragma unroll
      for (int ng = 0; ng < 4; ng++) {
        uint32_t r0, r1, r2, r3;
        asm volatile("ldmatrix.sync.aligned.m8n8.x4.shared.b16 {%0,%1,%2,%3}, [%4];"
                     : "=r"(r0), "=r"(r1), "=r"(r2), "=r"(r3)
                     : "r"(bbase + ng*16*APITCH + ks*32));
        bfr[2*ng][0]=r0; bfr[2*ng+1][0]=r1; bfr[2*ng][1]=r2; bfr[2*ng+1][1]=r3;
      }
      #pragma unroll
      for (int mt = 0; mt < 4; mt++) {
        uint32_t a0, a1, a2, a3;
        asm volatile("ldmatrix.sync.aligned.m8n8.x4.shared.b16 {%0,%1,%2,%3}, [%4];"
                     : "=r"(a0), "=r"(a1), "=r"(a2), "=r"(a3)
                     : "r"(abase + mt*16*APITCH + ks*32));
        #pragma unroll
        for (int nt = 0; nt < 8; nt++) {
          asm volatile("mma.sync.aligned.m16n8k32.row.col.f32.e4m3.e4m3.f32 "
                       "{%0,%1,%2,%3}, {%4,%5,%6,%7}, {%8,%9}, {%0,%1,%2,%3};"
                       : "+f"(acc[mt][nt][0]), "+f"(acc[mt][nt][1]),
                         "+f"(acc[mt][nt][2]), "+f"(acc[mt][nt][3])
                       : "r"(a0), "r"(a1), "r"(a2), "r"(a3),
                         "r"(bfr[nt][0]), "r"(bfr[nt][1]));
        }
      }
    }
    __syncthreads();
    if (kc + 2 < 4) PREFETCH(kc + 2)
  }

  const float sc = scale[0] * 0.015625f;   // /64 for the M8 scaling
  const float* xb = x   + ((size_t)b*CC + m0)*HWD + n0;
  float*       ob = out + ((size_t)b*CC + m0)*HWD + n0;
  const int er = l >> 2, ec = 2 * (l & 3);
  #pragma unroll
  for (int mt = 0; mt < 4; mt++) {
    #pragma unroll
    for (int nt = 0; nt < 8; nt++) {
      int row = wm + mt*16 + er;
      int col = wn + nt*8 + ec;
      size_t off = (size_t)row*HWD + col;
      float2 xv = *(const float2*)(xb + off);
      float2 ov; ov.x = xv.x + sc*acc[mt][nt][0]; ov.y = xv.y + sc*acc[mt][nt][1];
      *(float2*)(ob + off) = ov;
      size_t off2 = off + (size_t)8*HWD;
      float2 xv2 = *(const float2*)(xb + off2);
      float2 ov2; ov2.x = xv2.x + sc*acc[mt][nt][2]; ov2.y = xv2.y + sc*acc[mt][nt][3];
      *(float2*)(ob + off2) = ov2;
    }
  }
}

extern "C" void kernel_launch(void* const* d_in, const int* in_sizes, int n_in,
                              void* d_out, int out_size) {
  const float* x     = (const float*)d_in[0];
  const float* w1    = (const float*)d_in[1];
  const float* b1    = (const float*)d_in[2];
  const float* w2    = (const float*)d_in[3];
  const float* b2    = (const float*)d_in[4];
  const float* scale = (const float*)d_in[5];
  float* out = (float*)d_out;

  cudaFuncSetAttribute(k_sinkhorn, cudaFuncAttributeMaxDynamicSharedMemorySize, SMEM_SINK);
  cudaFuncSetAttribute(k_mix, cudaFuncAttributeMaxDynamicSharedMemorySize, SMEM_MIX);

  dim3 gpool(HWD/64, BB);
  k_poolT<<<gpool, 256>>>(x);
  k_fc1<<<BB, RR>>>(w1, b1);
  k_fc2_exp<<<CC, CC>>>(w2, b2);
  k_sinkhorn<<<BB, 1024, SMEM_SINK>>>();
  dim3 gmix(CC/128, HWD/256, BB);
  k_mix<<<gmix, 256, SMEM_MIX>>>(x, scale, out);
}

// round 7
// speedup vs baseline: 1.3633x; 1.0466x over previous
#include <cuda_runtime.h>
#include <cuda_bf16.h>
#include <cstdint>
#include <cstddef>

#define BB 32
#define CC 256
#define HWD 4096
#define RR 64

__device__ float g_pooled[BB*CC];
__device__ float g_h[BB*RR];
__device__ __nv_bfloat16 g_K0[(size_t)BB*CC*CC];
__device__ uint8_t g_M8[(size_t)BB*CC*CC];        // e4m3, M*64
__device__ uint8_t g_x8[(size_t)BB*HWD*CC];       // e4m3 x^T

__device__ __forceinline__ uint32_t s2u(const void* p) {
  return (uint32_t)__cvta_generic_to_shared(p);
}
__device__ __forceinline__ void cp16(uint32_t d, const void* s) {
  asm volatile("cp.async.cg.shared.global [%0], [%1], 16;" :: "r"(d), "l"(s));
}
__device__ __forceinline__ uint32_t fp8x2(float lo, float hi) {
  uint16_t r;
  asm("cvt.rn.satfinite.e4m3x2.f32 %0, %1, %2;" : "=h"(r) : "f"(hi), "f"(lo));
  return (uint32_t)r;
}

// ============ K1: transpose x -> e4m3 x8, partial pooled sums ============
__global__ void __launch_bounds__(256) k_poolT(const float* __restrict__ x) {
  __shared__ float ts[64*68];
  const int b = blockIdx.y, n0 = blockIdx.x * 64, t = threadIdx.x;
  const int rl = t >> 2, c4 = t & 3;
  const int nw = t & 63, cw = (t >> 6) * 16;
  for (int cg = 0; cg < 4; cg++) {
    int ch = cg*64 + rl;
    const float4* src = (const float4*)(x + ((size_t)b*CC + ch)*HWD + n0 + c4*16);
    float4 a = src[0], bq = src[1], cq = src[2], dq = src[3];
    float4* tr = (float4*)(ts + rl*68 + c4*16);
    tr[0]=a; tr[1]=bq; tr[2]=cq; tr[3]=dq;
    float s = (a.x+a.y+a.z+a.w) + (bq.x+bq.y+bq.z+bq.w)
            + (cq.x+cq.y+cq.z+cq.w) + (dq.x+dq.y+dq.z+dq.w);
    s += __shfl_xor_sync(0xffffffffu, s, 1);
    s += __shfl_xor_sync(0xffffffffu, s, 2);
    if (c4 == 0) atomicAdd(&g_pooled[b*CC + ch], s);
    __syncthreads();
    uint32_t pk[4];
    #pragma unroll
    for (int i = 0; i < 4; i++) {
      float v0 = ts[(cw + 4*i + 0)*68 + nw];
      float v1 = ts[(cw + 4*i + 1)*68 + nw];
      float v2 = ts[(cw + 4*i + 2)*68 + nw];
      float v3 = ts[(cw + 4*i + 3)*68 + nw];
      pk[i] = fp8x2(v0, v1) | (fp8x2(v2, v3) << 16);
    }
    uint8_t* dst = g_x8 + ((size_t)b*HWD + n0 + nw)*CC + cg*64 + cw;
    *(uint4*)dst = make_uint4(pk[0], pk[1], pk[2], pk[3]);
    __syncthreads();
  }
}

// ============ K2: h = silu(mean @ w1^T + b1); zero pooled for next replay ===
__global__ void k_fc1(const float* __restrict__ w1, const float* __restrict__ b1) {
  int b = blockIdx.x, r = threadIdx.x;
  __shared__ float p[CC];
  for (int k = r; k < CC; k += RR) p[k] = g_pooled[b*CC + k] * (1.0f/4096.0f);
  __syncthreads();
  for (int k = r; k < CC; k += RR) g_pooled[b*CC + k] = 0.f;
  const float4* wr = (const float4*)(w1 + (size_t)r * CC);
  float acc = b1[r];
  #pragma unroll 8
  for (int k = 0; k < 64; k++) {
    float4 w = wr[k];
    acc += w.x*p[4*k] + w.y*p[4*k+1] + w.z*p[4*k+2] + w.w*p[4*k+3];
  }
  g_h[b*RR + r] = acc / (1.0f + __expf(-acc));
}

// ============ K3: weights -> exp(w - rowmax) -> K0 (bf16) ============
__global__ void __launch_bounds__(256) k_fc2_exp(const float* __restrict__ w2,
                                                 const float* __restrict__ b2) {
  const int i = blockIdx.x, j = threadIdx.x;
  const int w = j >> 5, l = j & 31;
  __shared__ float hs[BB*RR];
  __shared__ float red[8*32];
  for (int tt = j; tt < BB*RR; tt += 256) hs[tt] = g_h[tt];
  __syncthreads();

  const float4* w2r = (const float4*)(w2 + (size_t)(i*CC + j) * RR);
  const float bv = b2[i*CC + j];
  float acc[32];
  #pragma unroll
  for (int b = 0; b < 32; b++) acc[b] = bv;
  #pragma unroll
  for (int k4 = 0; k4 < 16; k4++) {
    float4 wv = w2r[k4];
    #pragma unroll
    for (int b = 0; b < 32; b++) {
      const float* hb = hs + b*64 + k4*4;
      acc[b] += wv.x*hb[0] + wv.y*hb[1] + wv.z*hb[2] + wv.w*hb[3];
    }
  }
  #pragma unroll
  for (int b = 0; b < 32; b++) {
    float m = acc[b];
    #pragma unroll
    for (int o = 16; o; o >>= 1) m = fmaxf(m, __shfl_xor_sync(0xffffffffu, m, o));
    if (l == b) red[w*32 + b] = m;
  }
  __syncthreads();
  #pragma unroll
  for (int b = 0; b < 32; b++) {
    float bm = red[b];
    #pragma unroll
    for (int ww = 1; ww < 8; ww++) bm = fmaxf(bm, red[ww*32 + b]);
    float e = __expf(acc[b] - bm);
    float eo = __shfl_down_sync(0xffffffffu, e, 1);
    if ((j & 1) == 0) {
      __nv_bfloat162 pk;
      pk.x = __float2bfloat16(e); pk.y = __float2bfloat16(eo);
      *(__nv_bfloat162*)(g_K0 + ((size_t)(b*CC + i))*CC + j) = pk;
    }
  }
}

// ============ K4: Sinkhorn u/v scaling form, HFMA2 inner loops ============
#define KP 264
#define SMEM_SINK (256*KP*2 + 8*256*4 + 256*4 + 256*4 + 256*4 + 128*4)
__global__ void __launch_bounds__(1024, 1) k_sinkhorn() {
  extern __shared__ char smC[];
  __nv_bfloat16* Kb = (__nv_bfloat16*)smC;
  float* red = (float*)(smC + 256*KP*2);
  float* u = red + 8*256;
  float* v = u + 256;
  uint32_t* ub2 = (uint32_t*)(v + 256);   // (u_i, u_i) bf16x2
  uint32_t* vb2 = ub2 + 256;              // (v_2j, v_2j+1) bf16x2
  const int b = blockIdx.x, t = threadIdx.x;
  const __nv_bfloat16* src = g_K0 + (size_t)b * (CC*CC);
  #pragma unroll
  for (int i = 0; i < 8; i++) {
    int idx = t + 1024*i;
    int r = idx >> 5, c8 = idx & 31;
    float4 d = *(const float4*)(src + r*CC + c8*8);
    *(float4*)(Kb + r*KP + c8*8) = d;
  }
  if (t < 256) v[t] = 1.0f;
  if (t < 128) vb2[t] = 0x3F803F80u;   // bf16 (1.0, 1.0)
  __syncthreads();

  const int rr = t & 255, q = t >> 8;
  const int cp_ = t & 127, rg = t >> 7;
  const __nv_bfloat162 z2 = __floats2bfloat162_rn(0.f, 0.f);

  for (int it = 0; it < 20; it++) {
    // ---- row phase: partial (K v) over cols [q*64, q*64+64) ----
    {
      __nv_bfloat162 a8[8];
      #pragma unroll
      for (int a = 0; a < 8; a++) a8[a] = z2;
      const uint4* kp4 = (const uint4*)(Kb + rr*KP + q*64);
      const uint4* vp4 = (const uint4*)(vb2 + q*32);
      #pragma unroll
      for (int i = 0; i < 8; i++) {
        uint4 kk = kp4[i]; uint4 vv = vp4[i];
        const uint32_t* kw = &kk.x; const uint32_t* vw = &vv.x;
        #pragma unroll
        for (int j = 0; j < 4; j++) {
          a8[(i&1)*4+j] = __hfma2(*(const __nv_bfloat162*)&kw[j],
                                  *(const __nv_bfloat162*)&vw[j], a8[(i&1)*4+j]);
        }
      }
      float s = 0.f;
      #pragma unroll
      for (int a = 0; a < 8; a++) {
        float2 f = __bfloat1622float2(a8[a]);
        s += f.x + f.y;
      }
      red[q*256 + rr] = s;
    }
    __syncthreads();
    if (t < 256) {
      float s = red[t] + red[256+t] + red[512+t] + red[768+t];
      float uu = 1.0f / (s + 1e-12f);
      u[t] = uu;
      __nv_bfloat16 ub = __float2bfloat16(uu);
      __nv_bfloat162 up; up.x = ub; up.y = ub;
      ub2[t] = *(uint32_t*)&up;
    }
    __syncthreads();
    // ---- col phase: partial (K^T u) for col pair (2cp_, 2cp_+1), rows rg*32.. ----
    {
      __nv_bfloat162 a8[8];
      #pragma unroll
      for (int a = 0; a < 8; a++) a8[a] = z2;
      const __nv_bfloat16* base = Kb + (rg*32)*KP + 2*cp_;
      const uint32_t* up = ub2 + rg*32;
      #pragma unroll
      for (int i = 0; i < 32; i++) {
        uint32_t k2 = *(const uint32_t*)(base + i*KP);
        uint32_t uu = up[i];
        a8[i&7] = __hfma2(*(const __nv_bfloat162*)&k2,
                          *(const __nv_bfloat162*)&uu, a8[i&7]);
      }
      float a0 = 0.f, a1 = 0.f;
      #pragma unroll
      for (int a = 0; a < 8; a++) {
        float2 f = __bfloat1622float2(a8[a]);
        a0 += f.x; a1 += f.y;
      }
      float2 w2v; w2v.x = a0; w2v.y = a1;
      *(float2*)(red + rg*256 + 2*cp_) = w2v;
    }
    __syncthreads();
    if (t < 256) {
      float s = 0.f;
      #pragma unroll
      for (int g = 0; g < 8; g++) s += red[g*256 + t];
      float vv = 1.0f / (s + 1e-12f);
      v[t] = vv;
      float vn = __shfl_xor_sync(0xffffffffu, vv, 1);
      if ((t & 1) == 0) {
        __nv_bfloat162 vp; vp.x = __float2bfloat16(vv); vp.y = __float2bfloat16(vn);
        vb2[t >> 1] = *(uint32_t*)&vp;
      }
    }
    __syncthreads();
  }
  // write M8 = 64 * u_i * K0 * v_j as e4m3 (f32 u/v — full precision final pass)
  for (int idx = t; idx < 16384; idx += 1024) {
    int i = idx >> 6, c4 = idx & 63;
    float su = 64.0f * u[i];
    const __nv_bfloat16* rp = Kb + i*KP + 4*c4;
    float m0 = su * __bfloat162float(rp[0]) * v[4*c4+0];
    float m1 = su * __bfloat162float(rp[1]) * v[4*c4+1];
    float m2 = su * __bfloat162float(rp[2]) * v[4*c4+2];
    float m3 = su * __bfloat162float(rp[3]) * v[4*c4+3];
    uint32_t pk = fp8x2(m0, m1) | (fp8x2(m2, m3) << 16);
    *(uint32_t*)(g_M8 + (size_t)b*(CC*CC) + i*CC + 4*c4) = pk;
  }
}

// ============ K5: out = x + (scale/64) * M8 @ x8^T (e4m3 QMMA, 512 thr) =====
#define APITCH 80
#define ASTAGE (128*APITCH)
#define BSTAGE (256*APITCH)
#define SMEM_MIX (3*ASTAGE + 3*BSTAGE)
__global__ void __launch_bounds__(512, 1) k_mix(const float* __restrict__ x,
                                                const float* __restrict__ scale,
                                                float* __restrict__ out) {
  extern __shared__ __align__(128) char sm[];
  const int t = threadIdx.x;
  const int m0 = blockIdx.x * 128;
  const int n0 = blockIdx.y * 256;
  const int b  = blockIdx.z;
  const uint32_t s0 = s2u(sm);
  const int w = t >> 5, l = t & 31;
  const int wm = (w & 1) * 64, wn = (w >> 1) * 32;
  const int g = l >> 3, r = l & 7;
  const int lrow = r + (g & 1) * 8;
  const int lchunk = (g >> 1) * 16;

  const uint8_t* Ab = g_M8 + ((size_t)b << 16) + (size_t)m0 * CC;
  const uint8_t* Bb = g_x8 + ((size_t)b << 20) + (size_t)n0 * CC;

  #define PREFETCH(kc) {                                                        \
    uint32_t As_ = s0 + ((kc) % 3) * ASTAGE;                                    \
    uint32_t Bs_ = s0 + 3*ASTAGE + ((kc) % 3) * BSTAGE;                         \
    { int rw = t >> 2, c_ = t & 3;                                              \
      cp16(As_ + rw*APITCH + c_*16, Ab + (size_t)rw*CC + (kc)*64 + c_*16); }    \
    _Pragma("unroll")                                                           \
    for (int i_ = 0; i_ < 2; i_++) {                                            \
      int idx = t + 512*i_; int rw = idx >> 2, c_ = idx & 3;                    \
      cp16(Bs_ + rw*APITCH + c_*16, Bb + (size_t)rw*CC + (kc)*64 + c_*16);      \
    }                                                                           \
    asm volatile("cp.async.commit_group;");                                     \
  }

  float acc[4][4][4];
  #pragma unroll
  for (int mt = 0; mt < 4; mt++)
    #pragma unroll
    for (int nt = 0; nt < 4; nt++)
      #pragma unroll
      for (int qq = 0; qq < 4; qq++) acc[mt][nt][qq] = 0.f;

  PREFETCH(0)
  PREFETCH(1)

  for (int kc = 0; kc < 4; kc++) {
    if (kc < 3) asm volatile("cp.async.wait_group 1;" ::: "memory");
    else        asm volatile("cp.async.wait_group 0;" ::: "memory");
    __syncthreads();
    uint32_t Ast = s0 + (kc % 3) * ASTAGE;
    uint32_t Bst = s0 + 3*ASTAGE + (kc % 3) * BSTAGE;
    uint32_t abase = Ast + (uint32_t)(wm + lrow)*APITCH + lchunk;
    uint32_t bbase = Bst + (uint32_t)(wn + lrow)*APITCH + lchunk;
    #pragma unroll
    for (int ks = 0; ks < 2; ks++) {
      uint32_t bfr[4][2];
      #pragma unroll
      for (int ng = 0; ng < 2; ng++) {
        uint32_t r0, r1, r2, r3;
        asm volatile("ldmatrix.sync.aligned.m8n8.x4.shared.b16 {%0,%1,%2,%3}, [%4];"
                     : "=r"(r0), "=r"(r1), "=r"(r2), "=r"(r3)
                     : "r"(bbase + ng*16*APITCH + ks*32));
        bfr[2*ng][0]=r0; bfr[2*ng+1][0]=r1; bfr[2*ng][1]=r2; bfr[2*ng+1][1]=r3;
      }
      #pragma unroll
      for (int mt = 0; mt < 4; mt++) {
        uint32_t a0, a1, a2, a3;
        asm volatile("ldmatrix.sync.aligned.m8n8.x4.shared.b16 {%0,%1,%2,%3}, [%4];"
                     : "=r"(a0), "=r"(a1), "=r"(a2), "=r"(a3)
                     : "r"(abase + mt*16*APITCH + ks*32));
        #pragma unroll
        for (int nt = 0; nt < 4; nt++) {
          asm volatile("mma.sync.aligned.m16n8k32.row.col.f32.e4m3.e4m3.f32 "
                       "{%0,%1,%2,%3}, {%4,%5,%6,%7}, {%8,%9}, {%0,%1,%2,%3};"
                       : "+f"(acc[mt][nt][0]), "+f"(acc[mt][nt][1]),
                         "+f"(acc[mt][nt][2]), "+f"(acc[mt][nt][3])
                       : "r"(a0), "r"(a1), "r"(a2), "r"(a3),
                         "r"(bfr[nt][0]), "r"(bfr[nt][1]));
        }
      }
    }
    __syncthreads();
    if (kc + 2 < 4) PREFETCH(kc + 2)
  }

  const float sc = scale[0] * 0.015625f;
  const float* xb = x   + ((size_t)b*CC + m0)*HWD + n0;
  float*       ob = out + ((size_t)b*CC + m0)*HWD + n0;
  const int er = l >> 2, ec = 2 * (l & 3);
  #pragma unroll
  for (int mt = 0; mt < 4; mt++) {
    #pragma unroll
    for (int nt = 0; nt < 4; nt++) {
      int row = wm + mt*16 + er;
      int col = wn + nt*8 + ec;
      size_t off = (size_t)row*HWD + col;
      float2 xv = *(const float2*)(xb + off);
      float2 ov; ov.x = xv.x + sc*acc[mt][nt][0]; ov.y = xv.y + sc*acc[mt][nt][1];
      *(float2*)(ob + off) = ov;
      size_t off2 = off + (size_t)8*HWD;
      float2 xv2 = *(const float2*)(xb + off2);
      float2 ov2; ov2.x = xv2.x + sc*acc[mt][nt][2]; ov2.y = xv2.y + sc*acc[mt][nt][3];
      *(float2*)(ob + off2) = ov2;
    }
  }
}

extern "C" void kernel_launch(void* const* d_in, const int* in_sizes, int n_in,
                              void* d_out, int out_size) {
  const float* x     = (const float*)d_in[0];
  const float* w1    = (const float*)d_in[1];
  const float* b1    = (const float*)d_in[2];
  const float* w2    = (const float*)d_in[3];
  const float* b2    = (const float*)d_in[4];
  const float* scale = (const float*)d_in[5];
  float* out = (float*)d_out;

  cudaFuncSetAttribute(k_sinkhorn, cudaFuncAttributeMaxDynamicSharedMemorySize, SMEM_SINK);
  cudaFuncSetAttribute(k_mix, cudaFuncAttributeMaxDynamicSharedMemorySize, SMEM_MIX);

  dim3 gpool(HWD/64, BB);
  k_poolT<<<gpool, 256>>>(x);
  k_fc1<<<BB, RR>>>(w1, b1);
  k_fc2_exp<<<CC, CC>>>(w2, b2);
  k_sinkhorn<<<BB, 1024, SMEM_SINK>>>();
  dim3 gmix(CC/128, HWD/256, BB);
  k_mix<<<gmix, 512, SMEM_MIX>>>(x, scale, out);
}

// round 8
// speedup vs baseline: 1.4840x; 1.0885x over previous
#include <cuda_runtime.h>
#include <cuda_bf16.h>
#include <cstdint>
#include <cstddef>

#define BB 32
#define CC 256
#define HWD 4096
#define RR 64

__device__ float g_pooled[BB*CC];
__device__ float g_h[BB*RR];
__device__ __nv_bfloat16 g_K0[(size_t)BB*CC*CC];
__device__ uint8_t g_M8[(size_t)BB*CC*CC];        // e4m3, M*64
__device__ uint8_t g_x8[(size_t)BB*HWD*CC];       // e4m3 x^T

__device__ __forceinline__ uint32_t s2u(const void* p) {
  return (uint32_t)__cvta_generic_to_shared(p);
}
__device__ __forceinline__ void cp16(uint32_t d, const void* s) {
  asm volatile("cp.async.cg.shared.global [%0], [%1], 16;" :: "r"(d), "l"(s));
}
__device__ __forceinline__ uint32_t fp8x2(float lo, float hi) {
  uint16_t r;
  asm("cvt.rn.satfinite.e4m3x2.f32 %0, %1, %2;" : "=h"(r) : "f"(hi), "f"(lo));
  return (uint32_t)r;
}

// ============ K1: transpose x -> e4m3 x8, partial pooled sums ============
__global__ void __launch_bounds__(256) k_poolT(const float* __restrict__ x) {
  __shared__ float ts[64*68];
  const int b = blockIdx.y, n0 = blockIdx.x * 64, t = threadIdx.x;
  const int rl = t >> 2, c4 = t & 3;
  const int nw = t & 63, cw = (t >> 6) * 16;
  for (int cg = 0; cg < 4; cg++) {
    int ch = cg*64 + rl;
    const float4* src = (const float4*)(x + ((size_t)b*CC + ch)*HWD + n0 + c4*16);
    float4 a = src[0], bq = src[1], cq = src[2], dq = src[3];
    float4* tr = (float4*)(ts + rl*68 + c4*16);
    tr[0]=a; tr[1]=bq; tr[2]=cq; tr[3]=dq;
    float s = (a.x+a.y+a.z+a.w) + (bq.x+bq.y+bq.z+bq.w)
            + (cq.x+cq.y+cq.z+cq.w) + (dq.x+dq.y+dq.z+dq.w);
    s += __shfl_xor_sync(0xffffffffu, s, 1);
    s += __shfl_xor_sync(0xffffffffu, s, 2);
    if (c4 == 0) atomicAdd(&g_pooled[b*CC + ch], s);
    __syncthreads();
    uint32_t pk[4];
    #pragma unroll
    for (int i = 0; i < 4; i++) {
      float v0 = ts[(cw + 4*i + 0)*68 + nw];
      float v1 = ts[(cw + 4*i + 1)*68 + nw];
      float v2 = ts[(cw + 4*i + 2)*68 + nw];
      float v3 = ts[(cw + 4*i + 3)*68 + nw];
      pk[i] = fp8x2(v0, v1) | (fp8x2(v2, v3) << 16);
    }
    uint8_t* dst = g_x8 + ((size_t)b*HWD + n0 + nw)*CC + cg*64 + cw;
    *(uint4*)dst = make_uint4(pk[0], pk[1], pk[2], pk[3]);
    __syncthreads();
  }
}

// ============ K2: h = silu(mean @ w1^T + b1); zero pooled for next replay ===
__global__ void k_fc1(const float* __restrict__ w1, const float* __restrict__ b1) {
  int b = blockIdx.x, r = threadIdx.x;
  __shared__ float p[CC];
  for (int k = r; k < CC; k += RR) p[k] = g_pooled[b*CC + k] * (1.0f/4096.0f);
  __syncthreads();
  for (int k = r; k < CC; k += RR) g_pooled[b*CC + k] = 0.f;
  const float4* wr = (const float4*)(w1 + (size_t)r * CC);
  float acc = b1[r];
  #pragma unroll 8
  for (int k = 0; k < 64; k++) {
    float4 w = wr[k];
    acc += w.x*p[4*k] + w.y*p[4*k+1] + w.z*p[4*k+2] + w.w*p[4*k+3];
  }
  g_h[b*RR + r] = acc / (1.0f + __expf(-acc));
}

// ============ K3: weights -> exp(w - rowmax) -> K0; batch-split grid ========
__global__ void __launch_bounds__(256) k_fc2_exp(const float* __restrict__ w2,
                                                 const float* __restrict__ b2) {
  const int i = blockIdx.x, j = threadIdx.x;
  const int b0 = blockIdx.y * 16;              // 16 batches per block
  const int w = j >> 5, l = j & 31;
  __shared__ float hs[16*RR];
  __shared__ float red[8*16];
  for (int tt = j; tt < 16*RR; tt += 256) hs[tt] = g_h[b0*RR + tt];
  __syncthreads();

  const float4* w2r = (const float4*)(w2 + (size_t)(i*CC + j) * RR);
  const float bv = b2[i*CC + j];
  float acc[16];
  #pragma unroll
  for (int b = 0; b < 16; b++) acc[b] = bv;
  #pragma unroll
  for (int k4 = 0; k4 < 16; k4++) {
    float4 wv = w2r[k4];
    #pragma unroll
    for (int b = 0; b < 16; b++) {
      const float* hb = hs + b*64 + k4*4;
      acc[b] += wv.x*hb[0] + wv.y*hb[1] + wv.z*hb[2] + wv.w*hb[3];
    }
  }
  #pragma unroll
  for (int b = 0; b < 16; b++) {
    float m = acc[b];
    #pragma unroll
    for (int o = 16; o; o >>= 1) m = fmaxf(m, __shfl_xor_sync(0xffffffffu, m, o));
    if (l == b) red[w*16 + b] = m;
  }
  __syncthreads();
  #pragma unroll
  for (int b = 0; b < 16; b++) {
    float bm = red[b];
    #pragma unroll
    for (int ww = 1; ww < 8; ww++) bm = fmaxf(bm, red[ww*16 + b]);
    float e = __expf(acc[b] - bm);
    float eo = __shfl_down_sync(0xffffffffu, e, 1);
    if ((j & 1) == 0) {
      __nv_bfloat162 pk;
      pk.x = __float2bfloat16(e); pk.y = __float2bfloat16(eo);
      *(__nv_bfloat162*)(g_K0 + ((size_t)((b0 + b)*CC + i))*CC + j) = pk;
    }
  }
}

// ============ K4: Sinkhorn u/v scaling form, HFMA2 inner loops ============
#define KP 264
#define SMEM_SINK (256*KP*2 + 8*256*4 + 256*4 + 256*4 + 256*4 + 128*4)
__global__ void __launch_bounds__(1024, 1) k_sinkhorn() {
  extern __shared__ char smC[];
  __nv_bfloat16* Kb = (__nv_bfloat16*)smC;
  float* red = (float*)(smC + 256*KP*2);
  float* u = red + 8*256;
  float* v = u + 256;
  uint32_t* ub2 = (uint32_t*)(v + 256);
  uint32_t* vb2 = ub2 + 256;
  const int b = blockIdx.x, t = threadIdx.x;
  const __nv_bfloat16* src = g_K0 + (size_t)b * (CC*CC);
  #pragma unroll
  for (int i = 0; i < 8; i++) {
    int idx = t + 1024*i;
    int r = idx >> 5, c8 = idx & 31;
    float4 d = *(const float4*)(src + r*CC + c8*8);
    *(float4*)(Kb + r*KP + c8*8) = d;
  }
  if (t < 256) v[t] = 1.0f;
  if (t < 128) vb2[t] = 0x3F803F80u;
  __syncthreads();

  const int rr = t & 255, q = t >> 8;
  const int cp_ = t & 127, rg = t >> 7;
  const __nv_bfloat162 z2 = __floats2bfloat162_rn(0.f, 0.f);

  for (int it = 0; it < 20; it++) {
    {
      __nv_bfloat162 a8[8];
      #pragma unroll
      for (int a = 0; a < 8; a++) a8[a] = z2;
      const uint4* kp4 = (const uint4*)(Kb + rr*KP + q*64);
      const uint4* vp4 = (const uint4*)(vb2 + q*32);
      #pragma unroll
      for (int i = 0; i < 8; i++) {
        uint4 kk = kp4[i]; uint4 vv = vp4[i];
        const uint32_t* kw = &kk.x; const uint32_t* vw = &vv.x;
        #pragma unroll
        for (int j = 0; j < 4; j++) {
          a8[(i&1)*4+j] = __hfma2(*(const __nv_bfloat162*)&kw[j],
                                  *(const __nv_bfloat162*)&vw[j], a8[(i&1)*4+j]);
        }
      }
      float s = 0.f;
      #pragma unroll
      for (int a = 0; a < 8; a++) {
        float2 f = __bfloat1622float2(a8[a]);
        s += f.x + f.y;
      }
      red[q*256 + rr] = s;
    }
    __syncthreads();
    if (t < 256) {
      float s = red[t] + red[256+t] + red[512+t] + red[768+t];
      float uu = 1.0f / (s + 1e-12f);
      u[t] = uu;
      __nv_bfloat16 ub = __float2bfloat16(uu);
      __nv_bfloat162 up; up.x = ub; up.y = ub;
      ub2[t] = *(uint32_t*)&up;
    }
    __syncthreads();
    {
      __nv_bfloat162 a8[8];
      #pragma unroll
      for (int a = 0; a < 8; a++) a8[a] = z2;
      const __nv_bfloat16* base = Kb + (rg*32)*KP + 2*cp_;
      const uint32_t* up = ub2 + rg*32;
      #pragma unroll
      for (int i = 0; i < 32; i++) {
        uint32_t k2 = *(const uint32_t*)(base + i*KP);
        uint32_t uu = up[i];
        a8[i&7] = __hfma2(*(const __nv_bfloat162*)&k2,
                          *(const __nv_bfloat162*)&uu, a8[i&7]);
      }
      float a0 = 0.f, a1 = 0.f;
      #pragma unroll
      for (int a = 0; a < 8; a++) {
        float2 f = __bfloat1622float2(a8[a]);
        a0 += f.x; a1 += f.y;
      }
      float2 w2v; w2v.x = a0; w2v.y = a1;
      *(float2*)(red + rg*256 + 2*cp_) = w2v;
    }
    __syncthreads();
    if (t < 256) {
      float s = 0.f;
      #pragma unroll
      for (int g = 0; g < 8; g++) s += red[g*256 + t];
      float vv = 1.0f / (s + 1e-12f);
      v[t] = vv;
      float vn = __shfl_xor_sync(0xffffffffu, vv, 1);
      if ((t & 1) == 0) {
        __nv_bfloat162 vp; vp.x = __float2bfloat16(vv); vp.y = __float2bfloat16(vn);
        vb2[t >> 1] = *(uint32_t*)&vp;
      }
    }
    __syncthreads();
  }
  for (int idx = t; idx < 16384; idx += 1024) {
    int i = idx >> 6, c4 = idx & 63;
    float su = 64.0f * u[i];
    const __nv_bfloat16* rp = Kb + i*KP + 4*c4;
    float m0 = su * __bfloat162float(rp[0]) * v[4*c4+0];
    float m1 = su * __bfloat162float(rp[1]) * v[4*c4+1];
    float m2 = su * __bfloat162float(rp[2]) * v[4*c4+2];
    float m3 = su * __bfloat162float(rp[3]) * v[4*c4+3];
    uint32_t pk = fp8x2(m0, m1) | (fp8x2(m2, m3) << 16);
    *(uint32_t*)(g_M8 + (size_t)b*(CC*CC) + i*CC + 4*c4) = pk;
  }
}

// ============ K5: out = x + (scale/64)*M8@x8^T — 128x128 tile, 2 CTA/SM =====
#define APITCH 80
#define ASTG (128*APITCH)
#define STG (2*ASTG)            // A + B per stage
#define SMEM_MIX (2*STG)        // 2 stages = 40KB
__global__ void __launch_bounds__(256, 2) k_mix(const float* __restrict__ x,
                                                const float* __restrict__ scale,
                                                float* __restrict__ out) {
  extern __shared__ __align__(128) char sm[];
  const int t = threadIdx.x;
  const int m0 = blockIdx.x * 128;
  const int n0 = blockIdx.y * 128;
  const int b  = blockIdx.z;
  const uint32_t s0 = s2u(sm);
  const int w = t >> 5, l = t & 31;
  const int wm = (w & 1) * 64, wn = (w >> 1) * 32;
  const int g = l >> 3, r = l & 7;
  const int lrow = r + (g & 1) * 8;
  const int lchunk = (g >> 1) * 16;

  const uint8_t* Ab = g_M8 + ((size_t)b << 16) + (size_t)m0 * CC;
  const uint8_t* Bb = g_x8 + ((size_t)b << 20) + (size_t)n0 * CC;

  #define PREFETCH(kc) {                                                        \
    uint32_t As_ = s0 + ((kc) & 1) * STG;                                       \
    uint32_t Bs_ = As_ + ASTG;                                                  \
    _Pragma("unroll")                                                           \
    for (int i_ = 0; i_ < 2; i_++) {                                            \
      int idx = t + 256*i_; int rw = idx >> 2, c_ = idx & 3;                    \
      cp16(As_ + rw*APITCH + c_*16, Ab + (size_t)rw*CC + (kc)*64 + c_*16);      \
      cp16(Bs_ + rw*APITCH + c_*16, Bb + (size_t)rw*CC + (kc)*64 + c_*16);      \
    }                                                                           \
    asm volatile("cp.async.commit_group;");                                     \
  }

  float acc[4][4][4];
  #pragma unroll
  for (int mt = 0; mt < 4; mt++)
    #pragma unroll
    for (int nt = 0; nt < 4; nt++)
      #pragma unroll
      for (int qq = 0; qq < 4; qq++) acc[mt][nt][qq] = 0.f;

  PREFETCH(0)
  PREFETCH(1)

  for (int kc = 0; kc < 4; kc++) {
    if (kc < 3) asm volatile("cp.async.wait_group 1;" ::: "memory");
    else        asm volatile("cp.async.wait_group 0;" ::: "memory");
    __syncthreads();
    uint32_t Ast = s0 + (kc & 1) * STG;
    uint32_t Bst = Ast + ASTG;
    uint32_t abase = Ast + (uint32_t)(wm + lrow)*APITCH + lchunk;
    uint32_t bbase = Bst + (uint32_t)(wn + lrow)*APITCH + lchunk;
    #pragma unroll
    for (int ks = 0; ks < 2; ks++) {
      uint32_t bfr[4][2];
      #pragma unroll
      for (int ng = 0; ng < 2; ng++) {
        uint32_t r0, r1, r2, r3;
        asm volatile("ldmatrix.sync.aligned.m8n8.x4.shared.b16 {%0,%1,%2,%3}, [%4];"
                     : "=r"(r0), "=r"(r1), "=r"(r2), "=r"(r3)
                     : "r"(bbase + ng*16*APITCH + ks*32));
        bfr[2*ng][0]=r0; bfr[2*ng+1][0]=r1; bfr[2*ng][1]=r2; bfr[2*ng+1][1]=r3;
      }
      #pragma unroll
      for (int mt = 0; mt < 4; mt++) {
        uint32_t a0, a1, a2, a3;
        asm volatile("ldmatrix.sync.aligned.m8n8.x4.shared.b16 {%0,%1,%2,%3}, [%4];"
                     : "=r"(a0), "=r"(a1), "=r"(a2), "=r"(a3)
                     : "r"(abase + mt*16*APITCH + ks*32));
        #pragma unroll
        for (int nt = 0; nt < 4; nt++) {
          asm volatile("mma.sync.aligned.m16n8k32.row.col.f32.e4m3.e4m3.f32 "
                       "{%0,%1,%2,%3}, {%4,%5,%6,%7}, {%8,%9}, {%0,%1,%2,%3};"
                       : "+f"(acc[mt][nt][0]), "+f"(acc[mt][nt][1]),
                         "+f"(acc[mt][nt][2]), "+f"(acc[mt][nt][3])
                       : "r"(a0), "r"(a1), "r"(a2), "r"(a3),
                         "r"(bfr[nt][0]), "r"(bfr[nt][1]));
        }
      }
    }
    __syncthreads();
    if (kc + 2 < 4) PREFETCH(kc + 2)
  }

  const float sc = scale[0] * 0.015625f;
  const float* xb = x   + ((size_t)b*CC + m0)*HWD + n0;
  float*       ob = out + ((size_t)b*CC + m0)*HWD + n0;
  const int er = l >> 2, ec = 2 * (l & 3);
  #pragma unroll
  for (int mt = 0; mt < 4; mt++) {
    #pragma unroll
    for (int nt = 0; nt < 4; nt++) {
      int row = wm + mt*16 + er;
      int col = wn + nt*8 + ec;
      size_t off = (size_t)row*HWD + col;
      float2 xv = *(const float2*)(xb + off);
      float2 ov; ov.x = xv.x + sc*acc[mt][nt][0]; ov.y = xv.y + sc*acc[mt][nt][1];
      *(float2*)(ob + off) = ov;
      size_t off2 = off + (size_t)8*HWD;
      float2 xv2 = *(const float2*)(xb + off2);
      float2 ov2; ov2.x = xv2.x + sc*acc[mt][nt][2]; ov2.y = xv2.y + sc*acc[mt][nt][3];
      *(float2*)(ob + off2) = ov2;
    }
  }
}

extern "C" void kernel_launch(void* const* d_in, const int* in_sizes, int n_in,
                              void* d_out, int out_size) {
  const float* x     = (const float*)d_in[0];
  const float* w1    = (const float*)d_in[1];
  const float* b1    = (const float*)d_in[2];
  const float* w2    = (const float*)d_in[3];
  const float* b2    = (const float*)d_in[4];
  const float* scale = (const float*)d_in[5];
  float* out = (float*)d_out;

  cudaFuncSetAttribute(k_sinkhorn, cudaFuncAttributeMaxDynamicSharedMemorySize, SMEM_SINK);
  cudaFuncSetAttribute(k_mix, cudaFuncAttributeMaxDynamicSharedMemorySize, SMEM_MIX);

  dim3 gpool(HWD/64, BB);
  k_poolT<<<gpool, 256>>>(x);
  k_fc1<<<BB, RR>>>(w1, b1);
  dim3 gfc2(CC, 2);
  k_fc2_exp<<<gfc2, 256>>>(w2, b2);
  k_sinkhorn<<<BB, 1024, SMEM_SINK>>>();
  dim3 gmix(CC/128, HWD/128, BB);
  k_mix<<<gmix, 256, SMEM_MIX>>>(x, scale, out);
}